// round 8
// baseline (speedup 1.0000x reference)
#include <cuda_runtime.h>
#include <cuda_bf16.h>
#include <math.h>
#include <stdio.h>

#define DD 32
#define NP 32768
#define HH 64
#define MM 8
#define LL 4
#define KK 48
#define NOUT 4096
#define GH1 512
#define GH2 256
#define CANDCAP 96
#define R2 0.0036f
#define PI2 6.283185307179586f
#define FSC (1.0f/32768.0f)

// ---------------- device scratch ----------------
__device__ float  g_x[NP*HH];
__device__ float  g_y[NP*HH];
__device__ float2 g_s1[DD*DD*MM*HH];
__device__ float2 g_s2[DD*16*MM*HH];
__device__ float2 g_s3[16*16*MM*HH];
__device__ float2 g_s4[16*16*MM*HH];
__device__ float2 g_i1[DD*16*MM*HH];
__device__ float2 g_i2[DD*DD*MM*HH];
__device__ int    g_nbr[NOUT*KK];
__device__ int    g_cnt[NOUT];
__device__ float  g_gno[NOUT*HH];

__device__ __forceinline__ float dgelu(float x){
    float u = 0.7978845608028654f*(x + 0.044715f*x*x*x);
    return 0.5f*x*(1.0f + tanhf(u));
}

__global__ void k_zero(float* out, int n){
    int i = blockIdx.x*256 + threadIdx.x;
    if (i < n) out[i] = 0.f;
}

// ---------------- lift: 6 -> 256 (gelu) -> 64 ----------------
__global__ void __launch_bounds__(256) k_lift(const float* __restrict__ f,
                                              const float* __restrict__ in_p,
                                              const float* __restrict__ w1,
                                              const float* __restrict__ b1,
                                              const float* __restrict__ w2,
                                              const float* __restrict__ b2){
    __shared__ float s_in[8][6];
    __shared__ float s_h1[8*256];
    int t = threadIdx.x;
    int pb = blockIdx.x*8;
    if (t < 48){
        int pp = t/6, k = t%6;
        int p = pb + pp;
        s_in[pp][k] = (k < 3) ? f[p*3+k] : in_p[p*3+(k-3)];
    }
    __syncthreads();
    float bb = b1[t];
    for (int pp=0; pp<8; pp++){
        float h = bb;
        #pragma unroll
        for (int k=0;k<6;k++) h += s_in[pp][k]*w1[k*256+t];
        s_h1[pp*256+t] = dgelu(h);
    }
    __syncthreads();
    for (int r=0;r<2;r++){
        int e = t + r*256;
        int pp = e>>6, c = e&63;
        float acc = b2[c];
        const float* h1 = &s_h1[pp*256];
        for (int k=0;k<256;k++) acc += h1[k]*w2[k*64+c];
        g_x[(pb+pp)*64+c] = acc;
    }
}

// ---------------- forward z-DFT: real(32) -> 8 modes, scaled 1/32768 ----------------
__global__ void __launch_bounds__(256) k_fz(int sel){
    const float* cur = sel ? g_y : g_x;
    __shared__ float sx[32*64];
    __shared__ float twr[8*32], twi[8*32];
    int t = threadIdx.x, bx = blockIdx.x;   // bx = x*32+y
    for (int i=0;i<8;i++) sx[t+i*256] = cur[bx*2048 + t + i*256];
    {
        int kz = t>>5, z = t&31;
        float s,c; sincosf(-(PI2/32.f)*(float)((kz*z)&31), &s, &c);
        twr[t] = c*FSC; twi[t] = s*FSC;
    }
    __syncthreads();
    for (int r=0;r<2;r++){
        int e = t + r*256;
        int kz = e>>6, c = e&63;
        float re=0.f, im=0.f;
        #pragma unroll
        for (int z=0; z<32; z++){
            float v = sx[z*64+c];
            re += v*twr[kz*32+z];
            im += v*twi[kz*32+z];
        }
        g_s1[(bx*8+kz)*64+c] = make_float2(re, im);
    }
}

// ---------------- forward y-DFT: 32 -> 16 kept modes ----------------
__global__ void __launch_bounds__(256) k_fy(){
    __shared__ float2 sa[32*64];
    __shared__ float twr[16*32], twi[16*32];
    int t = threadIdx.x, bx = blockIdx.x;   // bx = x*8+kz
    int ix = bx>>3, kz = bx&7;
    for (int i=0;i<8;i++){
        int e = t + i*256; int yy = e>>6, c = e&63;
        sa[e] = g_s1[((ix*32+yy)*8+kz)*64+c];
    }
    for (int i=0;i<2;i++){
        int e = t + i*256; int m = e>>5, yy = e&31;
        int k = (m<8)?m:(m+16);
        float s,c; sincosf(-(PI2/32.f)*(float)((k*yy)&31), &s, &c);
        twr[e]=c; twi[e]=s;
    }
    __syncthreads();
    for (int r=0;r<4;r++){
        int e = t + r*256;
        int m = e>>6, c = e&63;
        float re=0.f, im=0.f;
        #pragma unroll
        for (int yy=0;yy<32;yy++){
            float2 a = sa[yy*64+c];
            float wr = twr[m*32+yy], wi = twi[m*32+yy];
            re += a.x*wr - a.y*wi;
            im += a.x*wi + a.y*wr;
        }
        g_s2[((ix*16+m)*8+kz)*64+c] = make_float2(re, im);
    }
}

// ---------------- forward x-DFT ----------------
__global__ void __launch_bounds__(256) k_fx(){
    __shared__ float2 sa[32*64];
    __shared__ float twr[16*32], twi[16*32];
    int t = threadIdx.x, bx = blockIdx.x;   // bx = ky*8+kz
    int ky = bx>>3, kz = bx&7;
    for (int i=0;i<8;i++){
        int e = t + i*256; int x = e>>6, c = e&63;
        sa[e] = g_s2[((x*16+ky)*8+kz)*64+c];
    }
    for (int i=0;i<2;i++){
        int e = t + i*256; int m = e>>5, x = e&31;
        int k = (m<8)?m:(m+16);
        float s,c; sincosf(-(PI2/32.f)*(float)((k*x)&31), &s, &c);
        twr[e]=c; twi[e]=s;
    }
    __syncthreads();
    for (int r=0;r<4;r++){
        int e = t + r*256;
        int m = e>>6, c = e&63;
        float re=0.f, im=0.f;
        #pragma unroll
        for (int x=0;x<32;x++){
            float2 a = sa[x*64+c];
            float wr = twr[m*32+x], wi = twi[m*32+x];
            re += a.x*wr - a.y*wi;
            im += a.x*wi + a.y*wr;
        }
        g_s3[((m*16+ky)*8+kz)*64+c] = make_float2(re, im);
    }
}

// ---------------- spectral multiply with REAL weights ----------------
// spec_w arrives as float32 (real part of complex64; harness dtype cast).
// Element index max = 33,554,431 == in_sizes[7]-1: provably in-bounds.
// blocks: 256 = ci(4) x mx(8) x my(8); threads 256 = oh(32) x mz(8); 2 o's/thread.
__global__ void __launch_bounds__(256) k_spec(const float* __restrict__ W, int l){
    __shared__ float2 sx[64*8];  // [i][mz]
    int t = threadIdx.x, b = blockIdx.x;
    int ci = b>>6, mx = (b>>3)&7, my = b&7;
    int hx = ci>>1, hy = ci&1;
    int gx = mx + 8*hx, gy = my + 8*hy;
    for (int e = t; e < 512; e += 256){
        int i = e>>3, mz = e&7;
        sx[i*8+mz] = g_s3[((gx*16+gy)*8+mz)*64 + i];
    }
    __syncthreads();
    int mz = t&7, oh = t>>3;               // oh in 0..31
    int moff = mx*64 + my*8 + mz;
    size_t base = (size_t)(l*4+ci)*64*64*512 + (size_t)moff;
    float ar1=0.f, ai1=0.f, ar2=0.f, ai2=0.f;
    for (int i=0;i<64;i++){
        float2 xv = sx[i*8+mz];
        size_t o0 = base + (size_t)i*32768;
        float w1 = W[o0 + (size_t)oh*512];
        float w2 = W[o0 + (size_t)(oh+32)*512];
        ar1 += xv.x*w1;  ai1 += xv.y*w1;
        ar2 += xv.x*w2;  ai2 += xv.y*w2;
    }
    g_s4[((gx*16+gy)*8+mz)*64 + oh]      = make_float2(ar1, ai1);
    g_s4[((gx*16+gy)*8+mz)*64 + oh + 32] = make_float2(ar2, ai2);
}

// ---------------- inverse x: 16 modes -> 32 positions ----------------
__global__ void __launch_bounds__(256) k_ix(){
    __shared__ float2 sa[16*64];
    __shared__ float twr[16*32], twi[16*32];
    int t = threadIdx.x, bx = blockIdx.x;   // bx = ky*8+kz
    int ky = bx>>3, kz = bx&7;
    for (int i=0;i<4;i++){
        int e = t + i*256; int m = e>>6, c = e&63;
        sa[e] = g_s4[((m*16+ky)*8+kz)*64+c];
    }
    for (int i=0;i<2;i++){
        int e = t + i*256; int m = e>>5, x = e&31;
        int k = (m<8)?m:(m+16);
        float s,c; sincosf((PI2/32.f)*(float)((k*x)&31), &s, &c);
        twr[e]=c; twi[e]=s;
    }
    __syncthreads();
    for (int r=0;r<8;r++){
        int e = t + r*256;
        int x = e>>6, c = e&63;
        float re=0.f, im=0.f;
        #pragma unroll
        for (int m=0;m<16;m++){
            float2 a = sa[m*64+c];
            float wr = twr[m*32+x], wi = twi[m*32+x];
            re += a.x*wr - a.y*wi;
            im += a.x*wi + a.y*wr;
        }
        g_i1[((x*16+ky)*8+kz)*64+c] = make_float2(re, im);
    }
}

// ---------------- inverse y ----------------
__global__ void __launch_bounds__(256) k_iy(){
    __shared__ float2 sa[16*64];
    __shared__ float twr[16*32], twi[16*32];
    int t = threadIdx.x, bx = blockIdx.x;   // bx = x*8+kz
    int x = bx>>3, kz = bx&7;
    for (int i=0;i<4;i++){
        int e = t + i*256; int m = e>>6, c = e&63;
        sa[e] = g_i1[((x*16+m)*8+kz)*64+c];
    }
    for (int i=0;i<2;i++){
        int e = t + i*256; int m = e>>5, yy = e&31;
        int k = (m<8)?m:(m+16);
        float s,c; sincosf((PI2/32.f)*(float)((k*yy)&31), &s, &c);
        twr[e]=c; twi[e]=s;
    }
    __syncthreads();
    for (int r=0;r<8;r++){
        int e = t + r*256;
        int yy = e>>6, c = e&63;
        float re=0.f, im=0.f;
        #pragma unroll
        for (int m=0;m<16;m++){
            float2 a = sa[m*64+c];
            float wr = twr[m*32+yy], wi = twi[m*32+yy];
            re += a.x*wr - a.y*wi;
            im += a.x*wi + a.y*wr;
        }
        g_i2[((x*32+yy)*8+kz)*64+c] = make_float2(re, im);
    }
}

// ---------------- inverse z (c2r) + spec_b + skip GEMM + skip_b + gelu ----------------
__global__ void __launch_bounds__(256) k_iz(const float* __restrict__ spec_b,
                                            const float* __restrict__ skip_w,
                                            const float* __restrict__ skip_b,
                                            int l, int sel){
    const float* cur = sel ? g_y : g_x;
    float* dst = sel ? g_x : g_y;
    __shared__ float2 sza[8*64];
    __shared__ float  sxi[32*64];
    __shared__ float  ssw[64*64];
    __shared__ float  twr[8*32], twi[8*32];
    int t = threadIdx.x, bx = blockIdx.x;   // bx = x*32+y
    for (int i=0;i<2;i++){ int e=t+i*256; sza[e] = g_i2[(bx*8+(e>>6))*64+(e&63)]; }
    for (int i=0;i<8;i++)  sxi[t+i*256] = cur[bx*2048 + t + i*256];
    for (int i=0;i<16;i++) ssw[t+i*256] = skip_w[l*4096 + t + i*256];
    {
        int kz = t>>5, z = t&31;
        float s,c; sincosf((PI2/32.f)*(float)((kz*z)&31), &s, &c);
        twr[t]=c; twi[t]=s;
    }
    __syncthreads();
    for (int r=0;r<8;r++){
        int e = t + r*256;
        int z = e>>6, c = e&63;
        float acc = sza[c].x;
        #pragma unroll
        for (int k=1;k<8;k++){
            float2 a = sza[k*64+c];
            acc += 2.f*(a.x*twr[k*32+z] - a.y*twi[k*32+z]);
        }
        acc += spec_b[l*64+c] + skip_b[l*64+c];
        float sk = 0.f;
        #pragma unroll 8
        for (int j=0;j<64;j++) sk += sxi[z*64+j]*ssw[j*64+c];
        float v = acc + sk;
        if (l < 3) v = dgelu(v);
        dst[bx*2048 + z*64 + c] = v;
    }
}

// ---------------- neighbor search ----------------
__global__ void __launch_bounds__(128) k_nbr(const float* __restrict__ in_p,
                                             const float* __restrict__ out_p){
    __shared__ float s_d2[CANDCAP];
    __shared__ int   s_idx[CANDCAP];
    __shared__ int   s_n;
    int t = threadIdx.x, q = blockIdx.x;
    float qx = out_p[q*3+0], qy = out_p[q*3+1], qz = out_p[q*3+2];
    if (t == 0) s_n = 0;
    __syncthreads();
    for (int p = t; p < NP; p += 128){
        float dx = qx - in_p[p*3+0];
        float dy = qy - in_p[p*3+1];
        float dz = qz - in_p[p*3+2];
        float d2 = dx*dx + dy*dy + dz*dz;
        if (d2 < R2){
            int pos = atomicAdd(&s_n, 1);
            if (pos < CANDCAP){ s_d2[pos] = d2; s_idx[pos] = p; }
        }
    }
    __syncthreads();
    int n = s_n; if (n > CANDCAP) n = CANDCAP;
    if (n > KK){
        if (t == 0){
            for (int j = 0; j < KK; j++){
                int mi = j; float mv = s_d2[j];
                for (int i = j+1; i < n; i++)
                    if (s_d2[i] < mv){ mv = s_d2[i]; mi = i; }
                float td = s_d2[j]; s_d2[j] = s_d2[mi]; s_d2[mi] = td;
                int   ti = s_idx[j]; s_idx[j] = s_idx[mi]; s_idx[mi] = ti;
            }
        }
        __syncthreads();
        n = KK;
    }
    if (t == 0) g_cnt[q] = n;
    if (t < KK) g_nbr[q*KK + t] = (t < n) ? s_idx[t] : 0;
}

// ---------------- GNO: per-query MLP 6->512->256->64, *fy, mean ----------------
extern __shared__ float gno_dyn[];
__global__ void __launch_bounds__(256) k_gno(const float* __restrict__ in_p,
                                             const float* __restrict__ out_p,
                                             const float* __restrict__ w1,
                                             const float* __restrict__ b1,
                                             const float* __restrict__ w2,
                                             const float* __restrict__ b2,
                                             const float* __restrict__ w3,
                                             const float* __restrict__ b3){
    float* s_h1 = gno_dyn;                 // 48*512
    float* s_h2 = gno_dyn + KK*GH1;        // 48*256
    __shared__ float s_w1[6*GH1];
    __shared__ float s_feat[KK*6];
    __shared__ float s_red[4*64];
    int t = threadIdx.x, q = blockIdx.x;
    int n = g_cnt[q];
    for (int e = t; e < 6*GH1; e += 256) s_w1[e] = w1[e];
    if (t < KK){
        int idx = g_nbr[q*KK + t];
        s_feat[t*6+0] = in_p[idx*3+0];
        s_feat[t*6+1] = in_p[idx*3+1];
        s_feat[t*6+2] = in_p[idx*3+2];
        s_feat[t*6+3] = out_p[q*3+0];
        s_feat[t*6+4] = out_p[q*3+1];
        s_feat[t*6+5] = out_p[q*3+2];
    }
    __syncthreads();
    for (int e = t; e < KK*GH1; e += 256){
        int p = e >> 9, c = e & 511;
        float v = 0.f;
        if (p < n){
            float h = b1[c];
            #pragma unroll
            for (int j=0;j<6;j++) h += s_feat[p*6+j]*s_w1[j*GH1+c];
            v = dgelu(h);
        }
        s_h1[e] = v;
    }
    __syncthreads();
    {
        int c = t;
        float acc[KK];
        #pragma unroll
        for (int p=0;p<KK;p++) acc[p] = 0.f;
        for (int k=0;k<GH1;k++){
            float wv = w2[k*GH2 + c];
            #pragma unroll
            for (int p=0;p<KK;p++) acc[p] += s_h1[p*GH1 + k]*wv;
        }
        float bb = b2[c];
        #pragma unroll
        for (int p=0;p<KK;p++) s_h2[p*GH2 + c] = dgelu(acc[p] + bb);
    }
    __syncthreads();
    {
        int c2 = t & 63, pg = t >> 6;
        float local = 0.f;
        for (int p = pg; p < n; p += 4){
            float a = b3[c2];
            for (int k=0;k<GH2;k++) a += s_h2[p*GH2 + k]*w3[k*64 + c2];
            int idx = g_nbr[q*KK + p];
            local += a * g_x[idx*64 + c2];
        }
        s_red[pg*64 + c2] = local;
    }
    __syncthreads();
    if (t < 64){
        float s = s_red[t] + s_red[64+t] + s_red[128+t] + s_red[192+t];
        float cd = (float)(n > 0 ? n : 1);
        g_gno[q*64 + t] = s / cd;
    }
}

// ---------------- projection: 64 -> 256 (gelu) -> 1 ----------------
__global__ void __launch_bounds__(256) k_proj(const float* __restrict__ pw1,
                                              const float* __restrict__ pb1,
                                              const float* __restrict__ pw2,
                                              const float* __restrict__ pb2,
                                              float* __restrict__ out){
    __shared__ float s_g[32*64];
    __shared__ float s_h[32*256];
    int t = threadIdx.x, qb = blockIdx.x*32;
    for (int i=0;i<8;i++) s_g[t+i*256] = g_gno[qb*64 + t + i*256];
    __syncthreads();
    int c = t;
    float b = pb1[c], wv = pw2[c];
    for (int q=0;q<32;q++){
        float acc = b;
        #pragma unroll 8
        for (int j=0;j<64;j++) acc += s_g[q*64+j]*pw1[j*256+c];
        s_h[q*256+c] = dgelu(acc)*wv;
    }
    __syncthreads();
    if (t < 32){
        float s = pb2[0];
        const float* hr = &s_h[t*256];
        for (int k=0;k<256;k++) s += hr[k];
        out[qb + t] = s;
    }
}

// ---------------- launch ----------------
extern "C" void kernel_launch(void* const* d_in, const int* in_sizes, int n_in,
                              void* d_out, int out_size){
    fprintf(stderr, "MANIFEST n_in=%d out_size=%d sizes=", n_in, out_size);
    for (int i = 0; i < n_in; i++) fprintf(stderr, "%d,", in_sizes[i]);
    fprintf(stderr, "\n");
    fflush(stderr);

    // Verified manifest (R7): dict order, spec_w = 33,554,432 float32 (real cast).
    static const int expA[21] = {98304,12288,98304,1536,256,16384,64,33554432,
                                 256,16384,256,3072,512,131072,256,16384,64,
                                 16384,256,256,1};
    float* out = (float*)d_out;
    int ok = (n_in == 21);
    for (int i = 0; i < 21 && ok; i++) if (in_sizes[i] != expA[i]) ok = 0;
    if (!ok){
        k_zero<<<(out_size + 255)/256, 256>>>(out, out_size);
        return;
    }

    const float* in_p  = (const float*)d_in[0];
    const float* out_p = (const float*)d_in[1];
    const float* f     = (const float*)d_in[2];
    const float* lw1   = (const float*)d_in[3];
    const float* lb1   = (const float*)d_in[4];
    const float* lw2   = (const float*)d_in[5];
    const float* lb2   = (const float*)d_in[6];
    const float* W     = (const float*)d_in[7];
    const float* specb = (const float*)d_in[8];
    const float* skw   = (const float*)d_in[9];
    const float* skb   = (const float*)d_in[10];
    const float* gw1   = (const float*)d_in[11];
    const float* gb1   = (const float*)d_in[12];
    const float* gw2   = (const float*)d_in[13];
    const float* gb2   = (const float*)d_in[14];
    const float* gw3   = (const float*)d_in[15];
    const float* gb3   = (const float*)d_in[16];
    const float* pw1   = (const float*)d_in[17];
    const float* pb1   = (const float*)d_in[18];
    const float* pw2   = (const float*)d_in[19];
    const float* pb2   = (const float*)d_in[20];

    int gno_smem = (KK*GH1 + KK*GH2) * (int)sizeof(float);  // 147456
    cudaFuncSetAttribute(k_gno, cudaFuncAttributeMaxDynamicSharedMemorySize, gno_smem);

    k_lift<<<NP/8, 256>>>(f, in_p, lw1, lb1, lw2, lb2);
    for (int l = 0; l < LL; l++){
        int sel = l & 1;  // 0: read g_x write g_y; 1: read g_y write g_x
        k_fz<<<1024, 256>>>(sel);
        k_fy<<<256, 256>>>();
        k_fx<<<128, 256>>>();
        k_spec<<<256, 256>>>(W, l);
        k_ix<<<128, 256>>>();
        k_iy<<<256, 256>>>();
        k_iz<<<1024, 256>>>(specb, skw, skb, l, sel);
    }
    // latent now in g_x (l=3 writes g_x)
    k_nbr<<<NOUT, 128>>>(in_p, out_p);
    k_gno<<<NOUT, 256, gno_smem>>>(in_p, out_p, gw1, gb1, gw2, gb2, gw3, gb3);
    k_proj<<<NOUT/32, 256>>>(pw1, pb1, pw2, pb2, out);
}

// round 9
// speedup vs baseline: 1.4668x; 1.4668x over previous
#include <cuda_runtime.h>
#include <cuda_bf16.h>
#include <math.h>

#define DD 32
#define NP 32768
#define HH 64
#define MM 8
#define LL 4
#define KK 48
#define NOUT 4096
#define GH1 512
#define GH2 256
#define CANDCAP 96
#define R2 0.0036f
#define PI2 6.283185307179586f
#define FSC (1.0f/32768.0f)
#define QPB 8          // queries per nbr block
#define KCH 128        // gno k-chunk

// ---------------- device scratch ----------------
__device__ float  g_x[NP*HH];
__device__ float  g_y[NP*HH];
__device__ float2 g_s1[DD*DD*MM*HH];
__device__ float2 g_s2[DD*16*MM*HH];
__device__ float2 g_s3[16*16*MM*HH];
__device__ float2 g_s4[16*16*MM*HH];
__device__ float2 g_i1[DD*16*MM*HH];
__device__ float2 g_i2[DD*DD*MM*HH];
__device__ int    g_nbr[NOUT*KK];
__device__ int    g_cnt[NOUT];
__device__ float  g_gno[NOUT*HH];

__device__ __forceinline__ float dgelu(float x){
    float u = 0.7978845608028654f*(x + 0.044715f*x*x*x);
    return 0.5f*x*(1.0f + tanhf(u));
}

__global__ void k_zero(float* out, int n){
    int i = blockIdx.x*256 + threadIdx.x;
    if (i < n) out[i] = 0.f;
}

// ---------------- lift: 6 -> 256 (gelu) -> 64 ----------------
__global__ void __launch_bounds__(256) k_lift(const float* __restrict__ f,
                                              const float* __restrict__ in_p,
                                              const float* __restrict__ w1,
                                              const float* __restrict__ b1,
                                              const float* __restrict__ w2,
                                              const float* __restrict__ b2){
    __shared__ float s_in[8][6];
    __shared__ float s_h1[8*256];
    int t = threadIdx.x;
    int pb = blockIdx.x*8;
    if (t < 48){
        int pp = t/6, k = t%6;
        int p = pb + pp;
        s_in[pp][k] = (k < 3) ? f[p*3+k] : in_p[p*3+(k-3)];
    }
    __syncthreads();
    float bb = b1[t];
    for (int pp=0; pp<8; pp++){
        float h = bb;
        #pragma unroll
        for (int k=0;k<6;k++) h += s_in[pp][k]*w1[k*256+t];
        s_h1[pp*256+t] = dgelu(h);
    }
    __syncthreads();
    for (int r=0;r<2;r++){
        int e = t + r*256;
        int pp = e>>6, c = e&63;
        float acc = b2[c];
        const float* h1 = &s_h1[pp*256];
        for (int k=0;k<256;k++) acc += h1[k]*w2[k*64+c];
        g_x[(pb+pp)*64+c] = acc;
    }
}

// ---------------- forward z-DFT: real(32) -> 8 modes, scaled 1/32768 ----------------
__global__ void __launch_bounds__(256) k_fz(int sel){
    const float* cur = sel ? g_y : g_x;
    __shared__ float sx[32*64];
    __shared__ float twr[8*32], twi[8*32];
    int t = threadIdx.x, bx = blockIdx.x;   // bx = x*32+y
    for (int i=0;i<8;i++) sx[t+i*256] = cur[bx*2048 + t + i*256];
    {
        int kz = t>>5, z = t&31;
        float s,c; sincosf(-(PI2/32.f)*(float)((kz*z)&31), &s, &c);
        twr[t] = c*FSC; twi[t] = s*FSC;
    }
    __syncthreads();
    for (int r=0;r<2;r++){
        int e = t + r*256;
        int kz = e>>6, c = e&63;
        float re=0.f, im=0.f;
        #pragma unroll
        for (int z=0; z<32; z++){
            float v = sx[z*64+c];
            re += v*twr[kz*32+z];
            im += v*twi[kz*32+z];
        }
        g_s1[(bx*8+kz)*64+c] = make_float2(re, im);
    }
}

// ---------------- forward y-DFT: 32 -> 16 kept modes ----------------
__global__ void __launch_bounds__(256) k_fy(){
    __shared__ float2 sa[32*64];
    __shared__ float twr[16*32], twi[16*32];
    int t = threadIdx.x, bx = blockIdx.x;   // bx = x*8+kz
    int ix = bx>>3, kz = bx&7;
    for (int i=0;i<8;i++){
        int e = t + i*256; int yy = e>>6, c = e&63;
        sa[e] = g_s1[((ix*32+yy)*8+kz)*64+c];
    }
    for (int i=0;i<2;i++){
        int e = t + i*256; int m = e>>5, yy = e&31;
        int k = (m<8)?m:(m+16);
        float s,c; sincosf(-(PI2/32.f)*(float)((k*yy)&31), &s, &c);
        twr[e]=c; twi[e]=s;
    }
    __syncthreads();
    for (int r=0;r<4;r++){
        int e = t + r*256;
        int m = e>>6, c = e&63;
        float re=0.f, im=0.f;
        #pragma unroll
        for (int yy=0;yy<32;yy++){
            float2 a = sa[yy*64+c];
            float wr = twr[m*32+yy], wi = twi[m*32+yy];
            re += a.x*wr - a.y*wi;
            im += a.x*wi + a.y*wr;
        }
        g_s2[((ix*16+m)*8+kz)*64+c] = make_float2(re, im);
    }
}

// ---------------- forward x-DFT ----------------
__global__ void __launch_bounds__(256) k_fx(){
    __shared__ float2 sa[32*64];
    __shared__ float twr[16*32], twi[16*32];
    int t = threadIdx.x, bx = blockIdx.x;   // bx = ky*8+kz
    int ky = bx>>3, kz = bx&7;
    for (int i=0;i<8;i++){
        int e = t + i*256; int x = e>>6, c = e&63;
        sa[e] = g_s2[((x*16+ky)*8+kz)*64+c];
    }
    for (int i=0;i<2;i++){
        int e = t + i*256; int m = e>>5, x = e&31;
        int k = (m<8)?m:(m+16);
        float s,c; sincosf(-(PI2/32.f)*(float)((k*x)&31), &s, &c);
        twr[e]=c; twi[e]=s;
    }
    __syncthreads();
    for (int r=0;r<4;r++){
        int e = t + r*256;
        int m = e>>6, c = e&63;
        float re=0.f, im=0.f;
        #pragma unroll
        for (int x=0;x<32;x++){
            float2 a = sa[x*64+c];
            float wr = twr[m*32+x], wi = twi[m*32+x];
            re += a.x*wr - a.y*wi;
            im += a.x*wi + a.y*wr;
        }
        g_s3[((m*16+ky)*8+kz)*64+c] = make_float2(re, im);
    }
}

// ---------------- spectral multiply with REAL weights ----------------
__global__ void __launch_bounds__(256) k_spec(const float* __restrict__ W, int l){
    __shared__ float2 sx[64*8];  // [i][mz]
    int t = threadIdx.x, b = blockIdx.x;
    int ci = b>>6, mx = (b>>3)&7, my = b&7;
    int hx = ci>>1, hy = ci&1;
    int gx = mx + 8*hx, gy = my + 8*hy;
    for (int e = t; e < 512; e += 256){
        int i = e>>3, mz = e&7;
        sx[i*8+mz] = g_s3[((gx*16+gy)*8+mz)*64 + i];
    }
    __syncthreads();
    int mz = t&7, oh = t>>3;               // oh in 0..31
    int moff = mx*64 + my*8 + mz;
    size_t base = (size_t)(l*4+ci)*64*64*512 + (size_t)moff;
    float ar1=0.f, ai1=0.f, ar2=0.f, ai2=0.f;
    for (int i=0;i<64;i++){
        float2 xv = sx[i*8+mz];
        size_t o0 = base + (size_t)i*32768;
        float w1 = W[o0 + (size_t)oh*512];
        float w2 = W[o0 + (size_t)(oh+32)*512];
        ar1 += xv.x*w1;  ai1 += xv.y*w1;
        ar2 += xv.x*w2;  ai2 += xv.y*w2;
    }
    g_s4[((gx*16+gy)*8+mz)*64 + oh]      = make_float2(ar1, ai1);
    g_s4[((gx*16+gy)*8+mz)*64 + oh + 32] = make_float2(ar2, ai2);
}

// ---------------- inverse x: 16 modes -> 32 positions ----------------
__global__ void __launch_bounds__(256) k_ix(){
    __shared__ float2 sa[16*64];
    __shared__ float twr[16*32], twi[16*32];
    int t = threadIdx.x, bx = blockIdx.x;   // bx = ky*8+kz
    int ky = bx>>3, kz = bx&7;
    for (int i=0;i<4;i++){
        int e = t + i*256; int m = e>>6, c = e&63;
        sa[e] = g_s4[((m*16+ky)*8+kz)*64+c];
    }
    for (int i=0;i<2;i++){
        int e = t + i*256; int m = e>>5, x = e&31;
        int k = (m<8)?m:(m+16);
        float s,c; sincosf((PI2/32.f)*(float)((k*x)&31), &s, &c);
        twr[e]=c; twi[e]=s;
    }
    __syncthreads();
    for (int r=0;r<8;r++){
        int e = t + r*256;
        int x = e>>6, c = e&63;
        float re=0.f, im=0.f;
        #pragma unroll
        for (int m=0;m<16;m++){
            float2 a = sa[m*64+c];
            float wr = twr[m*32+x], wi = twi[m*32+x];
            re += a.x*wr - a.y*wi;
            im += a.x*wi + a.y*wr;
        }
        g_i1[((x*16+ky)*8+kz)*64+c] = make_float2(re, im);
    }
}

// ---------------- inverse y ----------------
__global__ void __launch_bounds__(256) k_iy(){
    __shared__ float2 sa[16*64];
    __shared__ float twr[16*32], twi[16*32];
    int t = threadIdx.x, bx = blockIdx.x;   // bx = x*8+kz
    int x = bx>>3, kz = bx&7;
    for (int i=0;i<4;i++){
        int e = t + i*256; int m = e>>6, c = e&63;
        sa[e] = g_i1[((x*16+m)*8+kz)*64+c];
    }
    for (int i=0;i<2;i++){
        int e = t + i*256; int m = e>>5, yy = e&31;
        int k = (m<8)?m:(m+16);
        float s,c; sincosf((PI2/32.f)*(float)((k*yy)&31), &s, &c);
        twr[e]=c; twi[e]=s;
    }
    __syncthreads();
    for (int r=0;r<8;r++){
        int e = t + r*256;
        int yy = e>>6, c = e&63;
        float re=0.f, im=0.f;
        #pragma unroll
        for (int m=0;m<16;m++){
            float2 a = sa[m*64+c];
            float wr = twr[m*32+yy], wi = twi[m*32+yy];
            re += a.x*wr - a.y*wi;
            im += a.x*wi + a.y*wr;
        }
        g_i2[((x*32+yy)*8+kz)*64+c] = make_float2(re, im);
    }
}

// ---------------- inverse z (c2r) + spec_b + skip GEMM + skip_b + gelu ----------------
__global__ void __launch_bounds__(256) k_iz(const float* __restrict__ spec_b,
                                            const float* __restrict__ skip_w,
                                            const float* __restrict__ skip_b,
                                            int l, int sel){
    const float* cur = sel ? g_y : g_x;
    float* dst = sel ? g_x : g_y;
    __shared__ float2 sza[8*64];
    __shared__ float  sxi[32*64];
    __shared__ float  ssw[64*64];
    __shared__ float  twr[8*32], twi[8*32];
    int t = threadIdx.x, bx = blockIdx.x;   // bx = x*32+y
    for (int i=0;i<2;i++){ int e=t+i*256; sza[e] = g_i2[(bx*8+(e>>6))*64+(e&63)]; }
    for (int i=0;i<8;i++)  sxi[t+i*256] = cur[bx*2048 + t + i*256];
    for (int i=0;i<16;i++) ssw[t+i*256] = skip_w[l*4096 + t + i*256];
    {
        int kz = t>>5, z = t&31;
        float s,c; sincosf((PI2/32.f)*(float)((kz*z)&31), &s, &c);
        twr[t]=c; twi[t]=s;
    }
    __syncthreads();
    for (int r=0;r<8;r++){
        int e = t + r*256;
        int z = e>>6, c = e&63;
        float acc = sza[c].x;
        #pragma unroll
        for (int k=1;k<8;k++){
            float2 a = sza[k*64+c];
            acc += 2.f*(a.x*twr[k*32+z] - a.y*twi[k*32+z]);
        }
        acc += spec_b[l*64+c] + skip_b[l*64+c];
        float sk = 0.f;
        #pragma unroll 8
        for (int j=0;j<64;j++) sk += sxi[z*64+j]*ssw[j*64+c];
        float v = acc + sk;
        if (l < 3) v = dgelu(v);
        dst[bx*2048 + z*64 + c] = v;
    }
}

// ---------------- neighbor search: 8 queries per block ----------------
__global__ void __launch_bounds__(128) k_nbr(const float* __restrict__ in_p,
                                             const float* __restrict__ out_p){
    __shared__ float s_d2[QPB][CANDCAP];
    __shared__ int   s_idx[QPB][CANDCAP];
    __shared__ int   s_n[QPB];
    __shared__ float s_q[QPB][3];
    int t = threadIdx.x;
    int q0 = blockIdx.x*QPB;
    if (t < QPB*3) s_q[t/3][t%3] = out_p[(q0 + t/3)*3 + (t%3)];
    if (t < QPB) s_n[t] = 0;
    __syncthreads();
    for (int p = t; p < NP; p += 128){
        float px = in_p[p*3+0], py = in_p[p*3+1], pz = in_p[p*3+2];
        #pragma unroll
        for (int qi=0; qi<QPB; qi++){
            float dx = s_q[qi][0]-px, dy = s_q[qi][1]-py, dz = s_q[qi][2]-pz;
            float d2 = dx*dx + dy*dy + dz*dz;
            if (d2 < R2){
                int pos = atomicAdd(&s_n[qi], 1);
                if (pos < CANDCAP){ s_d2[qi][pos] = d2; s_idx[qi][pos] = p; }
            }
        }
    }
    __syncthreads();
    // per-query rank-select on overflow: thread qi handles query qi
    if (t < QPB){
        int qi = t;
        int n = s_n[qi]; if (n > CANDCAP) n = CANDCAP;
        if (n > KK){
            for (int j = 0; j < KK; j++){
                int mi = j; float mv = s_d2[qi][j];
                for (int i = j+1; i < n; i++)
                    if (s_d2[qi][i] < mv){ mv = s_d2[qi][i]; mi = i; }
                float td = s_d2[qi][j]; s_d2[qi][j] = s_d2[qi][mi]; s_d2[qi][mi] = td;
                int   ti = s_idx[qi][j]; s_idx[qi][j] = s_idx[qi][mi]; s_idx[qi][mi] = ti;
            }
            n = KK;
        }
        g_cnt[q0 + qi] = n;
        s_n[qi] = n;
    }
    __syncthreads();
    // write neighbor lists: 128 threads cover 8*48 = 384 entries
    for (int e = t; e < QPB*KK; e += 128){
        int qi = e / KK, j = e % KK;
        g_nbr[(q0+qi)*KK + j] = (j < s_n[qi]) ? s_idx[qi][j] : 0;
    }
}

// ---------------- GNO: chunked-h1, 2 blocks/SM ----------------
// dyn smem: h1 chunk 48*128 + h2 48*256 + w1 6*512 = 24KB+48KB+12KB = 84KB
extern __shared__ float gno_dyn[];
__global__ void __launch_bounds__(256) k_gno(const float* __restrict__ in_p,
                                             const float* __restrict__ out_p,
                                             const float* __restrict__ w1,
                                             const float* __restrict__ b1,
                                             const float* __restrict__ w2,
                                             const float* __restrict__ b2,
                                             const float* __restrict__ w3,
                                             const float* __restrict__ b3){
    float* s_h1c = gno_dyn;                      // KK*KCH
    float* s_h2  = gno_dyn + KK*KCH;             // KK*GH2
    float* s_w1  = gno_dyn + KK*KCH + KK*GH2;    // 6*GH1
    __shared__ float s_feat[KK*6];
    __shared__ float s_red[4*64];
    int t = threadIdx.x, q = blockIdx.x;
    int n = g_cnt[q];
    for (int e = t; e < 6*GH1; e += 256) s_w1[e] = w1[e];
    if (t < KK){
        int idx = g_nbr[q*KK + t];
        s_feat[t*6+0] = in_p[idx*3+0];
        s_feat[t*6+1] = in_p[idx*3+1];
        s_feat[t*6+2] = in_p[idx*3+2];
        s_feat[t*6+3] = out_p[q*3+0];
        s_feat[t*6+4] = out_p[q*3+1];
        s_feat[t*6+5] = out_p[q*3+2];
    }
    // layer2 accumulators (c = t): 48 registers, persist across chunks
    float acc[KK];
    #pragma unroll
    for (int p=0;p<KK;p++) acc[p] = 0.f;
    __syncthreads();

    for (int cc = 0; cc < GH1/KCH; cc++){
        // compute h1 chunk: entries p in [0,48), kk in [0,128)
        for (int e = t; e < KK*KCH; e += 256){
            int p = e / KCH, kk = e % KCH;
            int k = cc*KCH + kk;
            float v = 0.f;
            if (p < n){
                float h = b1[k];
                #pragma unroll
                for (int j=0;j<6;j++) h += s_feat[p*6+j]*s_w1[j*GH1+k];
                v = dgelu(h);
            }
            s_h1c[e] = v;
        }
        __syncthreads();
        // accumulate layer2 over this chunk: thread t = out channel c
        {
            int c = t;
            for (int kk=0; kk<KCH; kk++){
                float wv = w2[(cc*KCH+kk)*GH2 + c];
                #pragma unroll
                for (int p=0;p<KK;p++) acc[p] += s_h1c[p*KCH + kk]*wv;
            }
        }
        __syncthreads();
    }
    // h2 = gelu(acc + b2)
    {
        float bb = b2[t];
        #pragma unroll
        for (int p=0;p<KK;p++) s_h2[p*GH2 + t] = dgelu(acc[p] + bb);
    }
    __syncthreads();
    // layer3: thread (c2 = t&63, pg = t>>6) keeps 12 accumulators; w3 read once per k
    {
        int c2 = t & 63, pg = t >> 6;
        float a3[12];
        #pragma unroll
        for (int j=0;j<12;j++) a3[j] = 0.f;
        for (int k=0;k<GH2;k++){
            float wv = w3[k*64 + c2];
            #pragma unroll
            for (int j=0;j<12;j++) a3[j] += s_h2[(pg + 4*j)*GH2 + k]*wv;
        }
        float bb = b3[c2];
        float local = 0.f;
        #pragma unroll
        for (int j=0;j<12;j++){
            int p = pg + 4*j;
            if (p < n){
                int idx = g_nbr[q*KK + p];
                local += (a3[j] + bb) * g_x[idx*64 + c2];
            }
        }
        s_red[pg*64 + c2] = local;
    }
    __syncthreads();
    if (t < 64){
        float s = s_red[t] + s_red[64+t] + s_red[128+t] + s_red[192+t];
        float cd = (float)(n > 0 ? n : 1);
        g_gno[q*64 + t] = s / cd;
    }
}

// ---------------- projection: 64 -> 256 (gelu) -> 1 ----------------
__global__ void __launch_bounds__(256) k_proj(const float* __restrict__ pw1,
                                              const float* __restrict__ pb1,
                                              const float* __restrict__ pw2,
                                              const float* __restrict__ pb2,
                                              float* __restrict__ out){
    __shared__ float s_g[32*64];
    __shared__ float s_h[32*256];
    int t = threadIdx.x, qb = blockIdx.x*32;
    for (int i=0;i<8;i++) s_g[t+i*256] = g_gno[qb*64 + t + i*256];
    __syncthreads();
    int c = t;
    float b = pb1[c], wv = pw2[c];
    for (int q=0;q<32;q++){
        float acc = b;
        #pragma unroll 8
        for (int j=0;j<64;j++) acc += s_g[q*64+j]*pw1[j*256+c];
        s_h[q*256+c] = dgelu(acc)*wv;
    }
    __syncthreads();
    if (t < 32){
        float s = pb2[0];
        const float* hr = &s_h[t*256];
        for (int k=0;k<256;k++) s += hr[k];
        out[qb + t] = s;
    }
}

// ---------------- launch ----------------
extern "C" void kernel_launch(void* const* d_in, const int* in_sizes, int n_in,
                              void* d_out, int out_size){
    static const int expA[21] = {98304,12288,98304,1536,256,16384,64,33554432,
                                 256,16384,256,3072,512,131072,256,16384,64,
                                 16384,256,256,1};
    float* out = (float*)d_out;
    int ok = (n_in == 21);
    for (int i = 0; i < 21 && ok; i++) if (in_sizes[i] != expA[i]) ok = 0;
    if (!ok){
        k_zero<<<(out_size + 255)/256, 256>>>(out, out_size);
        return;
    }

    const float* in_p  = (const float*)d_in[0];
    const float* out_p = (const float*)d_in[1];
    const float* f     = (const float*)d_in[2];
    const float* lw1   = (const float*)d_in[3];
    const float* lb1   = (const float*)d_in[4];
    const float* lw2   = (const float*)d_in[5];
    const float* lb2   = (const float*)d_in[6];
    const float* W     = (const float*)d_in[7];
    const float* specb = (const float*)d_in[8];
    const float* skw   = (const float*)d_in[9];
    const float* skb   = (const float*)d_in[10];
    const float* gw1   = (const float*)d_in[11];
    const float* gb1   = (const float*)d_in[12];
    const float* gw2   = (const float*)d_in[13];
    const float* gb2   = (const float*)d_in[14];
    const float* gw3   = (const float*)d_in[15];
    const float* gb3   = (const float*)d_in[16];
    const float* pw1   = (const float*)d_in[17];
    const float* pb1   = (const float*)d_in[18];
    const float* pw2   = (const float*)d_in[19];
    const float* pb2   = (const float*)d_in[20];

    int gno_smem = (KK*KCH + KK*GH2 + 6*GH1) * (int)sizeof(float);  // 86016
    cudaFuncSetAttribute(k_gno, cudaFuncAttributeMaxDynamicSharedMemorySize, gno_smem);

    k_lift<<<NP/8, 256>>>(f, in_p, lw1, lb1, lw2, lb2);
    for (int l = 0; l < LL; l++){
        int sel = l & 1;  // 0: read g_x write g_y; 1: read g_y write g_x
        k_fz<<<1024, 256>>>(sel);
        k_fy<<<256, 256>>>();
        k_fx<<<128, 256>>>();
        k_spec<<<256, 256>>>(W, l);
        k_ix<<<128, 256>>>();
        k_iy<<<256, 256>>>();
        k_iz<<<1024, 256>>>(specb, skw, skb, l, sel);
    }
    // latent now in g_x (l=3 writes g_x)
    k_nbr<<<NOUT/QPB, 128>>>(in_p, out_p);
    k_gno<<<NOUT, 256, gno_smem>>>(in_p, out_p, gw1, gb1, gw2, gb2, gw3, gb3);
    k_proj<<<NOUT/32, 256>>>(pw1, pb1, pw2, pb2, out);
}

// round 10
// speedup vs baseline: 1.4829x; 1.0110x over previous
#include <cuda_runtime.h>
#include <cuda_bf16.h>
#include <math.h>

#define DD 32
#define NP 32768
#define HH 64
#define MM 8
#define LL 4
#define KK 48
#define NOUT 4096
#define GH1 512
#define GH2 256
#define CANDCAP 96
#define R2 0.0036f
#define PI2 6.283185307179586f
#define FSC (1.0f/32768.0f)
#define QPB 8          // queries per nbr block
#define KCH 128        // gno k-chunk
#define H2S 52         // h2 smem row stride (16B-aligned, conflict-reduced)

// ---------------- device scratch ----------------
__device__ float  g_x[NP*HH];
__device__ float  g_y[NP*HH];
__device__ float2 g_s1[DD*DD*MM*HH];
__device__ float2 g_s2[DD*16*MM*HH];
__device__ float2 g_s3[16*16*MM*HH];
__device__ float2 g_s4[16*16*MM*HH];
__device__ float2 g_i1[DD*16*MM*HH];
__device__ float2 g_i2[DD*DD*MM*HH];
__device__ int    g_nbr[NOUT*KK];
__device__ int    g_cnt[NOUT];
__device__ float  g_gno[NOUT*HH];

// gelu(x) = 0.5x(1+tanh(u)) = x * sigmoid(2u); exp-based -> always-fast MUFU path,
// accuracy ~1e-7 (better than MUFU.TANH), identical math to the tanh formula.
__device__ __forceinline__ float dgelu(float x){
    float u = 1.5957691216057308f*(x + 0.044715f*x*x*x);   // 2*0.7978845608...
    return x * __fdividef(1.f, 1.f + __expf(-u));
}

// twiddle: angle = sign * (2pi/32) * (m mod 32), folded to [-pi,pi] for __sincosf accuracy
__device__ __forceinline__ void tw32(int m, float sign, float* s, float* c){
    int km = ((m & 31) + 15 & 31) - 15;    // [-15,16]
    __sincosf(sign*(PI2/32.f)*(float)km, s, c);
}

__global__ void k_zero(float* out, int n){
    int i = blockIdx.x*256 + threadIdx.x;
    if (i < n) out[i] = 0.f;
}

// ---------------- lift: 6 -> 256 (gelu) -> 64 ----------------
__global__ void __launch_bounds__(256) k_lift(const float* __restrict__ f,
                                              const float* __restrict__ in_p,
                                              const float* __restrict__ w1,
                                              const float* __restrict__ b1,
                                              const float* __restrict__ w2,
                                              const float* __restrict__ b2){
    __shared__ float s_in[8][6];
    __shared__ float s_h1[8*256];
    int t = threadIdx.x;
    int pb = blockIdx.x*8;
    if (t < 48){
        int pp = t/6, k = t%6;
        int p = pb + pp;
        s_in[pp][k] = (k < 3) ? f[p*3+k] : in_p[p*3+(k-3)];
    }
    __syncthreads();
    float bb = b1[t];
    for (int pp=0; pp<8; pp++){
        float h = bb;
        #pragma unroll
        for (int k=0;k<6;k++) h += s_in[pp][k]*w1[k*256+t];
        s_h1[pp*256+t] = dgelu(h);
    }
    __syncthreads();
    for (int r=0;r<2;r++){
        int e = t + r*256;
        int pp = e>>6, c = e&63;
        float acc = b2[c];
        const float* h1 = &s_h1[pp*256];
        for (int k=0;k<256;k++) acc += h1[k]*w2[k*64+c];
        g_x[(pb+pp)*64+c] = acc;
    }
}

// ---------------- forward z-DFT: real(32) -> 8 modes, scaled 1/32768 ----------------
__global__ void __launch_bounds__(256) k_fz(int sel){
    const float* cur = sel ? g_y : g_x;
    __shared__ float sx[32*64];
    __shared__ float twr[8*32], twi[8*32];
    int t = threadIdx.x, bx = blockIdx.x;   // bx = x*32+y
    for (int i=0;i<8;i++) sx[t+i*256] = cur[bx*2048 + t + i*256];
    {
        int kz = t>>5, z = t&31;
        float s,c; tw32(kz*z, -1.f, &s, &c);
        twr[t] = c*FSC; twi[t] = s*FSC;
    }
    __syncthreads();
    for (int r=0;r<2;r++){
        int e = t + r*256;
        int kz = e>>6, c = e&63;
        float re=0.f, im=0.f;
        #pragma unroll
        for (int z=0; z<32; z++){
            float v = sx[z*64+c];
            re += v*twr[kz*32+z];
            im += v*twi[kz*32+z];
        }
        g_s1[(bx*8+kz)*64+c] = make_float2(re, im);
    }
}

// ---------------- forward y-DFT: 32 -> 16 kept modes ----------------
__global__ void __launch_bounds__(256) k_fy(){
    __shared__ float2 sa[32*64];
    __shared__ float twr[16*32], twi[16*32];
    int t = threadIdx.x, bx = blockIdx.x;   // bx = x*8+kz
    int ix = bx>>3, kz = bx&7;
    for (int i=0;i<8;i++){
        int e = t + i*256; int yy = e>>6, c = e&63;
        sa[e] = g_s1[((ix*32+yy)*8+kz)*64+c];
    }
    for (int i=0;i<2;i++){
        int e = t + i*256; int m = e>>5, yy = e&31;
        int k = (m<8)?m:(m+16);
        float s,c; tw32(k*yy, -1.f, &s, &c);
        twr[e]=c; twi[e]=s;
    }
    __syncthreads();
    for (int r=0;r<4;r++){
        int e = t + r*256;
        int m = e>>6, c = e&63;
        float re=0.f, im=0.f;
        #pragma unroll
        for (int yy=0;yy<32;yy++){
            float2 a = sa[yy*64+c];
            float wr = twr[m*32+yy], wi = twi[m*32+yy];
            re += a.x*wr - a.y*wi;
            im += a.x*wi + a.y*wr;
        }
        g_s2[((ix*16+m)*8+kz)*64+c] = make_float2(re, im);
    }
}

// ---------------- forward x-DFT ----------------
__global__ void __launch_bounds__(256) k_fx(){
    __shared__ float2 sa[32*64];
    __shared__ float twr[16*32], twi[16*32];
    int t = threadIdx.x, bx = blockIdx.x;   // bx = ky*8+kz
    int ky = bx>>3, kz = bx&7;
    for (int i=0;i<8;i++){
        int e = t + i*256; int x = e>>6, c = e&63;
        sa[e] = g_s2[((x*16+ky)*8+kz)*64+c];
    }
    for (int i=0;i<2;i++){
        int e = t + i*256; int m = e>>5, x = e&31;
        int k = (m<8)?m:(m+16);
        float s,c; tw32(k*x, -1.f, &s, &c);
        twr[e]=c; twi[e]=s;
    }
    __syncthreads();
    for (int r=0;r<4;r++){
        int e = t + r*256;
        int m = e>>6, c = e&63;
        float re=0.f, im=0.f;
        #pragma unroll
        for (int x=0;x<32;x++){
            float2 a = sa[x*64+c];
            float wr = twr[m*32+x], wi = twi[m*32+x];
            re += a.x*wr - a.y*wi;
            im += a.x*wi + a.y*wr;
        }
        g_s3[((m*16+ky)*8+kz)*64+c] = make_float2(re, im);
    }
}

// ---------------- spectral multiply with REAL weights ----------------
__global__ void __launch_bounds__(256) k_spec(const float* __restrict__ W, int l){
    __shared__ float2 sx[64*8];  // [i][mz]
    int t = threadIdx.x, b = blockIdx.x;
    int ci = b>>6, mx = (b>>3)&7, my = b&7;
    int hx = ci>>1, hy = ci&1;
    int gx = mx + 8*hx, gy = my + 8*hy;
    for (int e = t; e < 512; e += 256){
        int i = e>>3, mz = e&7;
        sx[i*8+mz] = g_s3[((gx*16+gy)*8+mz)*64 + i];
    }
    __syncthreads();
    int mz = t&7, oh = t>>3;               // oh in 0..31
    int moff = mx*64 + my*8 + mz;
    size_t base = (size_t)(l*4+ci)*64*64*512 + (size_t)moff;
    float ar1=0.f, ai1=0.f, ar2=0.f, ai2=0.f;
    for (int i=0;i<64;i++){
        float2 xv = sx[i*8+mz];
        size_t o0 = base + (size_t)i*32768;
        float w1 = W[o0 + (size_t)oh*512];
        float w2 = W[o0 + (size_t)(oh+32)*512];
        ar1 += xv.x*w1;  ai1 += xv.y*w1;
        ar2 += xv.x*w2;  ai2 += xv.y*w2;
    }
    g_s4[((gx*16+gy)*8+mz)*64 + oh]      = make_float2(ar1, ai1);
    g_s4[((gx*16+gy)*8+mz)*64 + oh + 32] = make_float2(ar2, ai2);
}

// ---------------- inverse x: 16 modes -> 32 positions ----------------
__global__ void __launch_bounds__(256) k_ix(){
    __shared__ float2 sa[16*64];
    __shared__ float twr[16*32], twi[16*32];
    int t = threadIdx.x, bx = blockIdx.x;   // bx = ky*8+kz
    int ky = bx>>3, kz = bx&7;
    for (int i=0;i<4;i++){
        int e = t + i*256; int m = e>>6, c = e&63;
        sa[e] = g_s4[((m*16+ky)*8+kz)*64+c];
    }
    for (int i=0;i<2;i++){
        int e = t + i*256; int m = e>>5, x = e&31;
        int k = (m<8)?m:(m+16);
        float s,c; tw32(k*x, 1.f, &s, &c);
        twr[e]=c; twi[e]=s;
    }
    __syncthreads();
    for (int r=0;r<8;r++){
        int e = t + r*256;
        int x = e>>6, c = e&63;
        float re=0.f, im=0.f;
        #pragma unroll
        for (int m=0;m<16;m++){
            float2 a = sa[m*64+c];
            float wr = twr[m*32+x], wi = twi[m*32+x];
            re += a.x*wr - a.y*wi;
            im += a.x*wi + a.y*wr;
        }
        g_i1[((x*16+ky)*8+kz)*64+c] = make_float2(re, im);
    }
}

// ---------------- inverse y ----------------
__global__ void __launch_bounds__(256) k_iy(){
    __shared__ float2 sa[16*64];
    __shared__ float twr[16*32], twi[16*32];
    int t = threadIdx.x, bx = blockIdx.x;   // bx = x*8+kz
    int x = bx>>3, kz = bx&7;
    for (int i=0;i<4;i++){
        int e = t + i*256; int m = e>>6, c = e&63;
        sa[e] = g_i1[((x*16+m)*8+kz)*64+c];
    }
    for (int i=0;i<2;i++){
        int e = t + i*256; int m = e>>5, yy = e&31;
        int k = (m<8)?m:(m+16);
        float s,c; tw32(k*yy, 1.f, &s, &c);
        twr[e]=c; twi[e]=s;
    }
    __syncthreads();
    for (int r=0;r<8;r++){
        int e = t + r*256;
        int yy = e>>6, c = e&63;
        float re=0.f, im=0.f;
        #pragma unroll
        for (int m=0;m<16;m++){
            float2 a = sa[m*64+c];
            float wr = twr[m*32+yy], wi = twi[m*32+yy];
            re += a.x*wr - a.y*wi;
            im += a.x*wi + a.y*wr;
        }
        g_i2[((x*32+yy)*8+kz)*64+c] = make_float2(re, im);
    }
}

// ---------------- inverse z (c2r) + spec_b + skip GEMM + skip_b + gelu ----------------
__global__ void __launch_bounds__(256) k_iz(const float* __restrict__ spec_b,
                                            const float* __restrict__ skip_w,
                                            const float* __restrict__ skip_b,
                                            int l, int sel){
    const float* cur = sel ? g_y : g_x;
    float* dst = sel ? g_x : g_y;
    __shared__ float2 sza[8*64];
    __shared__ float  sxi[32*64];
    __shared__ float  ssw[64*64];
    __shared__ float  twr[8*32], twi[8*32];
    int t = threadIdx.x, bx = blockIdx.x;   // bx = x*32+y
    for (int i=0;i<2;i++){ int e=t+i*256; sza[e] = g_i2[(bx*8+(e>>6))*64+(e&63)]; }
    for (int i=0;i<8;i++)  sxi[t+i*256] = cur[bx*2048 + t + i*256];
    for (int i=0;i<16;i++) ssw[t+i*256] = skip_w[l*4096 + t + i*256];
    {
        int kz = t>>5, z = t&31;
        float s,c; tw32(kz*z, 1.f, &s, &c);
        twr[t]=c; twi[t]=s;
    }
    __syncthreads();
    for (int r=0;r<8;r++){
        int e = t + r*256;
        int z = e>>6, c = e&63;
        float acc = sza[c].x;
        #pragma unroll
        for (int k=1;k<8;k++){
            float2 a = sza[k*64+c];
            acc += 2.f*(a.x*twr[k*32+z] - a.y*twi[k*32+z]);
        }
        acc += spec_b[l*64+c] + skip_b[l*64+c];
        float sk = 0.f;
        #pragma unroll 8
        for (int j=0;j<64;j++) sk += sxi[z*64+j]*ssw[j*64+c];
        float v = acc + sk;
        if (l < 3) v = dgelu(v);
        dst[bx*2048 + z*64 + c] = v;
    }
}

// ---------------- neighbor search: 8 queries per block ----------------
__global__ void __launch_bounds__(128) k_nbr(const float* __restrict__ in_p,
                                             const float* __restrict__ out_p){
    __shared__ float s_d2[QPB][CANDCAP];
    __shared__ int   s_idx[QPB][CANDCAP];
    __shared__ int   s_n[QPB];
    __shared__ float s_q[QPB][3];
    int t = threadIdx.x;
    int q0 = blockIdx.x*QPB;
    if (t < QPB*3) s_q[t/3][t%3] = out_p[(q0 + t/3)*3 + (t%3)];
    if (t < QPB) s_n[t] = 0;
    __syncthreads();
    for (int p = t; p < NP; p += 128){
        float px = in_p[p*3+0], py = in_p[p*3+1], pz = in_p[p*3+2];
        #pragma unroll
        for (int qi=0; qi<QPB; qi++){
            float dx = s_q[qi][0]-px, dy = s_q[qi][1]-py, dz = s_q[qi][2]-pz;
            float d2 = dx*dx + dy*dy + dz*dz;
            if (d2 < R2){
                int pos = atomicAdd(&s_n[qi], 1);
                if (pos < CANDCAP){ s_d2[qi][pos] = d2; s_idx[qi][pos] = p; }
            }
        }
    }
    __syncthreads();
    if (t < QPB){
        int qi = t;
        int n = s_n[qi]; if (n > CANDCAP) n = CANDCAP;
        if (n > KK){
            for (int j = 0; j < KK; j++){
                int mi = j; float mv = s_d2[qi][j];
                for (int i = j+1; i < n; i++)
                    if (s_d2[qi][i] < mv){ mv = s_d2[qi][i]; mi = i; }
                float td = s_d2[qi][j]; s_d2[qi][j] = s_d2[qi][mi]; s_d2[qi][mi] = td;
                int   ti = s_idx[qi][j]; s_idx[qi][j] = s_idx[qi][mi]; s_idx[qi][mi] = ti;
            }
            n = KK;
        }
        g_cnt[q0 + qi] = n;
        s_n[qi] = n;
    }
    __syncthreads();
    for (int e = t; e < QPB*KK; e += 128){
        int qi = e / KK, j = e % KK;
        g_nbr[(q0+qi)*KK + j] = (j < s_n[qi]) ? s_idx[qi][j] : 0;
    }
}

// ---------------- GNO: transposed h1, LDS.128, n-skip ----------------
// dyn smem floats: h1c [KCH][48]=6144, h2 [GH2][H2S]=13312, w1 6*512=3072  -> 90112 B
extern __shared__ float gno_dyn[];
__global__ void __launch_bounds__(256) k_gno(const float* __restrict__ in_p,
                                             const float* __restrict__ out_p,
                                             const float* __restrict__ w1,
                                             const float* __restrict__ b1,
                                             const float* __restrict__ w2,
                                             const float* __restrict__ b2,
                                             const float* __restrict__ w3,
                                             const float* __restrict__ b3){
    float* s_h1c = gno_dyn;                      // [kk][48]
    float* s_h2  = gno_dyn + KK*KCH;             // [k][H2S]
    float* s_w1  = gno_dyn + KK*KCH + GH2*H2S;   // 6*GH1
    __shared__ float s_feat[KK*6];
    __shared__ float s_red[4*64];
    int t = threadIdx.x, q = blockIdx.x;
    int n = g_cnt[q];
    for (int e = t; e < 6*GH1; e += 256) s_w1[e] = w1[e];
    if (t < KK){
        int idx = g_nbr[q*KK + t];
        s_feat[t*6+0] = in_p[idx*3+0];
        s_feat[t*6+1] = in_p[idx*3+1];
        s_feat[t*6+2] = in_p[idx*3+2];
        s_feat[t*6+3] = out_p[q*3+0];
        s_feat[t*6+4] = out_p[q*3+1];
        s_feat[t*6+5] = out_p[q*3+2];
    }
    float acc[KK];
    #pragma unroll
    for (int p=0;p<KK;p++) acc[p] = 0.f;
    __syncthreads();

    for (int cc = 0; cc < GH1/KCH; cc++){
        // layer1 chunk -> s_h1c[kk*48+p]; contiguous writes (e = kk*48+p)
        for (int e = t; e < KK*KCH; e += 256){
            int kk = e / KK, p = e - kk*KK;
            int k = cc*KCH + kk;
            float v = 0.f;
            if (p < n){
                float h = b1[k];
                #pragma unroll
                for (int j=0;j<6;j++) h += s_feat[p*6+j]*s_w1[j*GH1+k];
                v = dgelu(h);
            }
            s_h1c[e] = v;
        }
        __syncthreads();
        // layer2: thread t = out channel c; p-chunks of 8 with uniform skip
        {
            const float* w2c = w2 + (size_t)cc*KCH*GH2 + t;
            #pragma unroll
            for (int pc = 0; pc < 6; pc++){
                if (pc*8 < n){
                    #pragma unroll 2
                    for (int kk=0; kk<KCH; kk++){
                        float wv = w2c[(size_t)kk*GH2];
                        const float4 a = *(const float4*)&s_h1c[kk*KK + pc*8];
                        const float4 b = *(const float4*)&s_h1c[kk*KK + pc*8 + 4];
                        acc[pc*8+0] += a.x*wv; acc[pc*8+1] += a.y*wv;
                        acc[pc*8+2] += a.z*wv; acc[pc*8+3] += a.w*wv;
                        acc[pc*8+4] += b.x*wv; acc[pc*8+5] += b.y*wv;
                        acc[pc*8+6] += b.z*wv; acc[pc*8+7] += b.w*wv;
                    }
                }
            }
        }
        __syncthreads();
    }
    // h2 = gelu(acc + b2), transposed store [k][p]
    {
        float bb = b2[t];
        #pragma unroll
        for (int p=0;p<KK;p++){
            float v = 0.f;
            if (p < n) v = dgelu(acc[p] + bb);
            s_h2[t*H2S + p] = v;
        }
    }
    __syncthreads();
    // layer3: thread (c2 = t&63, pg = t>>6) owns 12 contiguous p; LDS.128 on h2
    {
        int c2 = t & 63, pg = t >> 6;
        float local = 0.f;
        if (pg*12 < n){
            float a3[12];
            #pragma unroll
            for (int j=0;j<12;j++) a3[j] = 0.f;
            const float* w3c = w3 + c2;
            for (int k=0;k<GH2;k++){
                float wv = w3c[(size_t)k*64];
                const float* hr = &s_h2[k*H2S + pg*12];
                const float4 h0 = *(const float4*)(hr);
                const float4 h1 = *(const float4*)(hr+4);
                const float4 h2v = *(const float4*)(hr+8);
                a3[0] += h0.x*wv; a3[1] += h0.y*wv; a3[2] += h0.z*wv; a3[3] += h0.w*wv;
                a3[4] += h1.x*wv; a3[5] += h1.y*wv; a3[6] += h1.z*wv; a3[7] += h1.w*wv;
                a3[8] += h2v.x*wv; a3[9] += h2v.y*wv; a3[10] += h2v.z*wv; a3[11] += h2v.w*wv;
            }
            float bb = b3[c2];
            #pragma unroll
            for (int j=0;j<12;j++){
                int p = pg*12 + j;
                if (p < n){
                    int idx = g_nbr[q*KK + p];
                    local += (a3[j] + bb) * g_x[idx*64 + c2];
                }
            }
        }
        s_red[pg*64 + c2] = local;
    }
    __syncthreads();
    if (t < 64){
        float s = s_red[t] + s_red[64+t] + s_red[128+t] + s_red[192+t];
        float cd = (float)(n > 0 ? n : 1);
        g_gno[q*64 + t] = s / cd;
    }
}

// ---------------- projection: 64 -> 256 (gelu) -> 1 ----------------
__global__ void __launch_bounds__(256) k_proj(const float* __restrict__ pw1,
                                              const float* __restrict__ pb1,
                                              const float* __restrict__ pw2,
                                              const float* __restrict__ pb2,
                                              float* __restrict__ out){
    __shared__ float s_g[32*64];
    __shared__ float s_h[32*256];
    int t = threadIdx.x, qb = blockIdx.x*32;
    for (int i=0;i<8;i++) s_g[t+i*256] = g_gno[qb*64 + t + i*256];
    __syncthreads();
    int c = t;
    float b = pb1[c], wv = pw2[c];
    for (int q=0;q<32;q++){
        float acc = b;
        #pragma unroll 8
        for (int j=0;j<64;j++) acc += s_g[q*64+j]*pw1[j*256+c];
        s_h[q*256+c] = dgelu(acc)*wv;
    }
    __syncthreads();
    if (t < 32){
        float s = pb2[0];
        const float* hr = &s_h[t*256];
        for (int k=0;k<256;k++) s += hr[k];
        out[qb + t] = s;
    }
}

// ---------------- launch ----------------
extern "C" void kernel_launch(void* const* d_in, const int* in_sizes, int n_in,
                              void* d_out, int out_size){
    static const int expA[21] = {98304,12288,98304,1536,256,16384,64,33554432,
                                 256,16384,256,3072,512,131072,256,16384,64,
                                 16384,256,256,1};
    float* out = (float*)d_out;
    int ok = (n_in == 21);
    for (int i = 0; i < 21 && ok; i++) if (in_sizes[i] != expA[i]) ok = 0;
    if (!ok){
        k_zero<<<(out_size + 255)/256, 256>>>(out, out_size);
        return;
    }

    const float* in_p  = (const float*)d_in[0];
    const float* out_p = (const float*)d_in[1];
    const float* f     = (const float*)d_in[2];
    const float* lw1   = (const float*)d_in[3];
    const float* lb1   = (const float*)d_in[4];
    const float* lw2   = (const float*)d_in[5];
    const float* lb2   = (const float*)d_in[6];
    const float* W     = (const float*)d_in[7];
    const float* specb = (const float*)d_in[8];
    const float* skw   = (const float*)d_in[9];
    const float* skb   = (const float*)d_in[10];
    const float* gw1   = (const float*)d_in[11];
    const float* gb1   = (const float*)d_in[12];
    const float* gw2   = (const float*)d_in[13];
    const float* gb2   = (const float*)d_in[14];
    const float* gw3   = (const float*)d_in[15];
    const float* gb3   = (const float*)d_in[16];
    const float* pw1   = (const float*)d_in[17];
    const float* pb1   = (const float*)d_in[18];
    const float* pw2   = (const float*)d_in[19];
    const float* pb2   = (const float*)d_in[20];

    int gno_smem = (KK*KCH + GH2*H2S + 6*GH1) * (int)sizeof(float);  // 90112
    cudaFuncSetAttribute(k_gno, cudaFuncAttributeMaxDynamicSharedMemorySize, gno_smem);

    k_lift<<<NP/8, 256>>>(f, in_p, lw1, lb1, lw2, lb2);
    for (int l = 0; l < LL; l++){
        int sel = l & 1;  // 0: read g_x write g_y; 1: read g_y write g_x
        k_fz<<<1024, 256>>>(sel);
        k_fy<<<256, 256>>>();
        k_fx<<<128, 256>>>();
        k_spec<<<256, 256>>>(W, l);
        k_ix<<<128, 256>>>();
        k_iy<<<256, 256>>>();
        k_iz<<<1024, 256>>>(specb, skw, skb, l, sel);
    }
    // latent now in g_x (l=3 writes g_x)
    k_nbr<<<NOUT/QPB, 128>>>(in_p, out_p);
    k_gno<<<NOUT, 256, gno_smem>>>(in_p, out_p, gw1, gb1, gw2, gb2, gw3, gb3);
    k_proj<<<NOUT/32, 256>>>(pw1, pb1, pw2, pb2, out);
}

// round 12
// speedup vs baseline: 2.7947x; 1.8846x over previous
#include <cuda_runtime.h>
#include <cuda_bf16.h>
#include <math.h>

#define DD 32
#define NP 32768
#define HH 64
#define MM 8
#define LL 4
#define KK 48
#define NOUT 4096
#define GH1 512
#define GH2 256
#define CANDCAP 96
#define R2 0.0036f
#define PI2 6.283185307179586f
#define FSC (1.0f/32768.0f)
#define QPB 8          // queries per nbr block
#define KCH 64         // gno k-chunk
#define H2S 52         // h2 smem row stride (16B-aligned, 4-way store conflicts)

// ---------------- device scratch ----------------
__device__ float  g_x[NP*HH];
__device__ float  g_y[NP*HH];
__device__ float2 g_s1[DD*DD*MM*HH];
__device__ float2 g_s2[DD*16*MM*HH];
__device__ float2 g_s3[16*16*MM*HH];
__device__ float2 g_s4[16*16*MM*HH];
__device__ float2 g_i1[DD*16*MM*HH];
__device__ float2 g_i2[DD*DD*MM*HH];
__device__ int    g_nbr[NOUT*KK];
__device__ int    g_cnt[NOUT];
__device__ float  g_gno[NOUT*HH];

// gelu(x) = x * sigmoid(2u); exp-based fast path, ~1e-7 accuracy.
__device__ __forceinline__ float dgelu(float x){
    float u = 1.5957691216057308f*(x + 0.044715f*x*x*x);
    return x * __fdividef(1.f, 1.f + __expf(-u));
}

// twiddle folded to [-pi,pi]
__device__ __forceinline__ void tw32(int m, float sign, float* s, float* c){
    int km = ((m & 31) + 15 & 31) - 15;
    __sincosf(sign*(PI2/32.f)*(float)km, s, c);
}

__global__ void k_zero(float* out, int n){
    int i = blockIdx.x*256 + threadIdx.x;
    if (i < n) out[i] = 0.f;
}

// ---------------- lift: 6 -> 256 (gelu) -> 64 ----------------
__global__ void __launch_bounds__(256) k_lift(const float* __restrict__ f,
                                              const float* __restrict__ in_p,
                                              const float* __restrict__ w1,
                                              const float* __restrict__ b1,
                                              const float* __restrict__ w2,
                                              const float* __restrict__ b2){
    __shared__ float s_in[8][6];
    __shared__ float s_h1[8*256];
    int t = threadIdx.x;
    int pb = blockIdx.x*8;
    if (t < 48){
        int pp = t/6, k = t%6;
        int p = pb + pp;
        s_in[pp][k] = (k < 3) ? f[p*3+k] : in_p[p*3+(k-3)];
    }
    __syncthreads();
    float bb = b1[t];
    for (int pp=0; pp<8; pp++){
        float h = bb;
        #pragma unroll
        for (int k=0;k<6;k++) h += s_in[pp][k]*w1[k*256+t];
        s_h1[pp*256+t] = dgelu(h);
    }
    __syncthreads();
    for (int r=0;r<2;r++){
        int e = t + r*256;
        int pp = e>>6, c = e&63;
        float acc = b2[c];
        const float* h1 = &s_h1[pp*256];
        for (int k=0;k<256;k++) acc += h1[k]*w2[k*64+c];
        g_x[(pb+pp)*64+c] = acc;
    }
}

// ---------------- forward z-DFT ----------------
__global__ void __launch_bounds__(256) k_fz(int sel){
    const float* cur = sel ? g_y : g_x;
    __shared__ float sx[32*64];
    __shared__ float twr[8*32], twi[8*32];
    int t = threadIdx.x, bx = blockIdx.x;
    for (int i=0;i<8;i++) sx[t+i*256] = cur[bx*2048 + t + i*256];
    {
        int kz = t>>5, z = t&31;
        float s,c; tw32(kz*z, -1.f, &s, &c);
        twr[t] = c*FSC; twi[t] = s*FSC;
    }
    __syncthreads();
    for (int r=0;r<2;r++){
        int e = t + r*256;
        int kz = e>>6, c = e&63;
        float re=0.f, im=0.f;
        #pragma unroll
        for (int z=0; z<32; z++){
            float v = sx[z*64+c];
            re += v*twr[kz*32+z];
            im += v*twi[kz*32+z];
        }
        g_s1[(bx*8+kz)*64+c] = make_float2(re, im);
    }
}

// ---------------- forward y-DFT ----------------
__global__ void __launch_bounds__(256) k_fy(){
    __shared__ float2 sa[32*64];
    __shared__ float twr[16*32], twi[16*32];
    int t = threadIdx.x, bx = blockIdx.x;
    int ix = bx>>3, kz = bx&7;
    for (int i=0;i<8;i++){
        int e = t + i*256; int yy = e>>6, c = e&63;
        sa[e] = g_s1[((ix*32+yy)*8+kz)*64+c];
    }
    for (int i=0;i<2;i++){
        int e = t + i*256; int m = e>>5, yy = e&31;
        int k = (m<8)?m:(m+16);
        float s,c; tw32(k*yy, -1.f, &s, &c);
        twr[e]=c; twi[e]=s;
    }
    __syncthreads();
    for (int r=0;r<4;r++){
        int e = t + r*256;
        int m = e>>6, c = e&63;
        float re=0.f, im=0.f;
        #pragma unroll
        for (int yy=0;yy<32;yy++){
            float2 a = sa[yy*64+c];
            float wr = twr[m*32+yy], wi = twi[m*32+yy];
            re += a.x*wr - a.y*wi;
            im += a.x*wi + a.y*wr;
        }
        g_s2[((ix*16+m)*8+kz)*64+c] = make_float2(re, im);
    }
}

// ---------------- forward x-DFT ----------------
__global__ void __launch_bounds__(256) k_fx(){
    __shared__ float2 sa[32*64];
    __shared__ float twr[16*32], twi[16*32];
    int t = threadIdx.x, bx = blockIdx.x;
    int ky = bx>>3, kz = bx&7;
    for (int i=0;i<8;i++){
        int e = t + i*256; int x = e>>6, c = e&63;
        sa[e] = g_s2[((x*16+ky)*8+kz)*64+c];
    }
    for (int i=0;i<2;i++){
        int e = t + i*256; int m = e>>5, x = e&31;
        int k = (m<8)?m:(m+16);
        float s,c; tw32(k*x, -1.f, &s, &c);
        twr[e]=c; twi[e]=s;
    }
    __syncthreads();
    for (int r=0;r<4;r++){
        int e = t + r*256;
        int m = e>>6, c = e&63;
        float re=0.f, im=0.f;
        #pragma unroll
        for (int x=0;x<32;x++){
            float2 a = sa[x*64+c];
            float wr = twr[m*32+x], wi = twi[m*32+x];
            re += a.x*wr - a.y*wi;
            im += a.x*wi + a.y*wr;
        }
        g_s3[((m*16+ky)*8+kz)*64+c] = make_float2(re, im);
    }
}

// ---------------- spectral multiply, REAL weights; 512 blocks for parallelism ----------------
__global__ void __launch_bounds__(256) k_spec(const float* __restrict__ W, int l){
    __shared__ float2 sx[64*8];  // [i][mz]
    int t = threadIdx.x, b = blockIdx.x;
    int half = b & 1, bb = b >> 1;
    int ci = bb>>6, mx = (bb>>3)&7, my = bb&7;
    int hx = ci>>1, hy = ci&1;
    int gx = mx + 8*hx, gy = my + 8*hy;
    for (int e = t; e < 512; e += 256){
        int i = e>>3, mz = e&7;
        sx[i*8+mz] = g_s3[((gx*16+gy)*8+mz)*64 + i];
    }
    __syncthreads();
    int mz = t&7, oh = (t>>3) + half*32;   // 0..63
    int moff = mx*64 + my*8 + mz;
    size_t base = (size_t)(l*4+ci)*64*64*512 + (size_t)moff + (size_t)oh*512;
    float ar=0.f, ai=0.f;
    #pragma unroll 8
    for (int i=0;i<64;i++){
        float2 xv = sx[i*8+mz];
        float w = W[base + (size_t)i*32768];
        ar += xv.x*w;  ai += xv.y*w;
    }
    g_s4[((gx*16+gy)*8+mz)*64 + oh] = make_float2(ar, ai);
}

// ---------------- inverse x ----------------
__global__ void __launch_bounds__(256) k_ix(){
    __shared__ float2 sa[16*64];
    __shared__ float twr[16*32], twi[16*32];
    int t = threadIdx.x, bx = blockIdx.x;
    int ky = bx>>3, kz = bx&7;
    for (int i=0;i<4;i++){
        int e = t + i*256; int m = e>>6, c = e&63;
        sa[e] = g_s4[((m*16+ky)*8+kz)*64+c];
    }
    for (int i=0;i<2;i++){
        int e = t + i*256; int m = e>>5, x = e&31;
        int k = (m<8)?m:(m+16);
        float s,c; tw32(k*x, 1.f, &s, &c);
        twr[e]=c; twi[e]=s;
    }
    __syncthreads();
    for (int r=0;r<8;r++){
        int e = t + r*256;
        int x = e>>6, c = e&63;
        float re=0.f, im=0.f;
        #pragma unroll
        for (int m=0;m<16;m++){
            float2 a = sa[m*64+c];
            float wr = twr[m*32+x], wi = twi[m*32+x];
            re += a.x*wr - a.y*wi;
            im += a.x*wi + a.y*wr;
        }
        g_i1[((x*16+ky)*8+kz)*64+c] = make_float2(re, im);
    }
}

// ---------------- inverse y ----------------
__global__ void __launch_bounds__(256) k_iy(){
    __shared__ float2 sa[16*64];
    __shared__ float twr[16*32], twi[16*32];
    int t = threadIdx.x, bx = blockIdx.x;
    int x = bx>>3, kz = bx&7;
    for (int i=0;i<4;i++){
        int e = t + i*256; int m = e>>6, c = e&63;
        sa[e] = g_i1[((x*16+m)*8+kz)*64+c];
    }
    for (int i=0;i<2;i++){
        int e = t + i*256; int m = e>>5, yy = e&31;
        int k = (m<8)?m:(m+16);
        float s,c; tw32(k*yy, 1.f, &s, &c);
        twr[e]=c; twi[e]=s;
    }
    __syncthreads();
    for (int r=0;r<8;r++){
        int e = t + r*256;
        int yy = e>>6, c = e&63;
        float re=0.f, im=0.f;
        #pragma unroll
        for (int m=0;m<16;m++){
            float2 a = sa[m*64+c];
            float wr = twr[m*32+yy], wi = twi[m*32+yy];
            re += a.x*wr - a.y*wi;
            im += a.x*wi + a.y*wr;
        }
        g_i2[((x*32+yy)*8+kz)*64+c] = make_float2(re, im);
    }
}

// ---------------- inverse z (c2r) + spec_b + skip GEMM + skip_b + gelu ----------------
__global__ void __launch_bounds__(256) k_iz(const float* __restrict__ spec_b,
                                            const float* __restrict__ skip_w,
                                            const float* __restrict__ skip_b,
                                            int l, int sel){
    const float* cur = sel ? g_y : g_x;
    float* dst = sel ? g_x : g_y;
    __shared__ float2 sza[8*64];
    __shared__ float  sxi[32*64];
    __shared__ float  ssw[64*64];
    __shared__ float  twr[8*32], twi[8*32];
    int t = threadIdx.x, bx = blockIdx.x;
    for (int i=0;i<2;i++){ int e=t+i*256; sza[e] = g_i2[(bx*8+(e>>6))*64+(e&63)]; }
    for (int i=0;i<8;i++)  sxi[t+i*256] = cur[bx*2048 + t + i*256];
    for (int i=0;i<16;i++) ssw[t+i*256] = skip_w[l*4096 + t + i*256];
    {
        int kz = t>>5, z = t&31;
        float s,c; tw32(kz*z, 1.f, &s, &c);
        twr[t]=c; twi[t]=s;
    }
    __syncthreads();
    for (int r=0;r<8;r++){
        int e = t + r*256;
        int z = e>>6, c = e&63;
        float acc = sza[c].x;
        #pragma unroll
        for (int k=1;k<8;k++){
            float2 a = sza[k*64+c];
            acc += 2.f*(a.x*twr[k*32+z] - a.y*twi[k*32+z]);
        }
        acc += spec_b[l*64+c] + skip_b[l*64+c];
        float sk = 0.f;
        #pragma unroll 8
        for (int j=0;j<64;j++) sk += sxi[z*64+j]*ssw[j*64+c];
        float v = acc + sk;
        if (l < 3) v = dgelu(v);
        dst[bx*2048 + z*64 + c] = v;
    }
}

// ---------------- neighbor search: 8 queries per block ----------------
__global__ void __launch_bounds__(128) k_nbr(const float* __restrict__ in_p,
                                             const float* __restrict__ out_p){
    __shared__ float s_d2[QPB][CANDCAP];
    __shared__ int   s_idx[QPB][CANDCAP];
    __shared__ int   s_n[QPB];
    __shared__ float s_q[QPB][3];
    int t = threadIdx.x;
    int q0 = blockIdx.x*QPB;
    if (t < QPB*3) s_q[t/3][t%3] = out_p[(q0 + t/3)*3 + (t%3)];
    if (t < QPB) s_n[t] = 0;
    __syncthreads();
    for (int p = t; p < NP; p += 128){
        float px = in_p[p*3+0], py = in_p[p*3+1], pz = in_p[p*3+2];
        #pragma unroll
        for (int qi=0; qi<QPB; qi++){
            float dx = s_q[qi][0]-px, dy = s_q[qi][1]-py, dz = s_q[qi][2]-pz;
            float d2 = dx*dx + dy*dy + dz*dz;
            if (d2 < R2){
                int pos = atomicAdd(&s_n[qi], 1);
                if (pos < CANDCAP){ s_d2[qi][pos] = d2; s_idx[qi][pos] = p; }
            }
        }
    }
    __syncthreads();
    if (t < QPB){
        int qi = t;
        int n = s_n[qi]; if (n > CANDCAP) n = CANDCAP;
        if (n > KK){
            for (int j = 0; j < KK; j++){
                int mi = j; float mv = s_d2[qi][j];
                for (int i = j+1; i < n; i++)
                    if (s_d2[qi][i] < mv){ mv = s_d2[qi][i]; mi = i; }
                float td = s_d2[qi][j]; s_d2[qi][j] = s_d2[qi][mi]; s_d2[qi][mi] = td;
                int   ti = s_idx[qi][j]; s_idx[qi][j] = s_idx[qi][mi]; s_idx[qi][mi] = ti;
            }
            n = KK;
        }
        g_cnt[q0 + qi] = n;
        s_n[qi] = n;
    }
    __syncthreads();
    for (int e = t; e < QPB*KK; e += 128){
        int qi = e / KK, j = e % KK;
        g_nbr[(q0+qi)*KK + j] = (j < s_n[qi]) ? s_idx[qi][j] : 0;
    }
}

// ---------------- GNO layers 1+2, templated on active p-chunks ----------------
template<int NPC>
__device__ __forceinline__ void gno_l12(const float* __restrict__ w1,
                                        const float* __restrict__ b1,
                                        const float* __restrict__ w2,
                                        int t, int n,
                                        const float* s_feat, float* s_h1c,
                                        float (&acc)[KK]){
    for (int cc = 0; cc < GH1/KCH; cc++){
        // layer1 chunk -> s_h1c[kk*48+p]
        for (int e = t; e < KK*KCH; e += 256){
            int kk = e / KK, p = e - kk*KK;
            int k = cc*KCH + kk;
            float v = 0.f;
            if (p < n){
                float h = b1[k];
                #pragma unroll
                for (int j=0;j<6;j++) h += s_feat[p*6+j]*w1[j*GH1+k];
                v = dgelu(h);
            }
            s_h1c[e] = v;
        }
        __syncthreads();
        // layer2: thread t = out channel; w2 loaded once per kk; h1 warp-broadcast LDS.128
        const float* w2c = w2 + (size_t)cc*KCH*GH2 + t;
        #pragma unroll 2
        for (int kk=0; kk<KCH; kk++){
            float wv = w2c[(size_t)kk*GH2];
            const float* h1r = &s_h1c[kk*KK];
            #pragma unroll
            for (int pc = 0; pc < NPC; pc++){
                const float4 a = *(const float4*)&h1r[pc*8];
                const float4 b = *(const float4*)&h1r[pc*8 + 4];
                acc[pc*8+0] += a.x*wv; acc[pc*8+1] += a.y*wv;
                acc[pc*8+2] += a.z*wv; acc[pc*8+3] += a.w*wv;
                acc[pc*8+4] += b.x*wv; acc[pc*8+5] += b.y*wv;
                acc[pc*8+6] += b.z*wv; acc[pc*8+7] += b.w*wv;
            }
        }
        __syncthreads();
    }
}

// dyn smem floats: h1c [KCH][48]=3072, h2 [GH2][H2S]=13312  -> 65536 B
extern __shared__ float gno_dyn[];
__global__ void __launch_bounds__(256, 3) k_gno(const float* __restrict__ in_p,
                                                const float* __restrict__ out_p,
                                                const float* __restrict__ w1,
                                                const float* __restrict__ b1,
                                                const float* __restrict__ w2,
                                                const float* __restrict__ b2,
                                                const float* __restrict__ w3,
                                                const float* __restrict__ b3){
    float* s_h1c = gno_dyn;                 // [kk][48]
    float* s_h2  = gno_dyn + KK*KCH;        // [k][H2S]
    __shared__ float s_feat[KK*6];
    __shared__ float s_red[4*64];
    int t = threadIdx.x, q = blockIdx.x;
    int n = g_cnt[q];
    if (t < KK){
        int idx = g_nbr[q*KK + t];
        s_feat[t*6+0] = in_p[idx*3+0];
        s_feat[t*6+1] = in_p[idx*3+1];
        s_feat[t*6+2] = in_p[idx*3+2];
        s_feat[t*6+3] = out_p[q*3+0];
        s_feat[t*6+4] = out_p[q*3+1];
        s_feat[t*6+5] = out_p[q*3+2];
    }
    float acc[KK];
    #pragma unroll
    for (int p=0;p<KK;p++) acc[p] = 0.f;
    __syncthreads();

    int npc = (n + 7) >> 3;
    switch (npc){
        case 1: gno_l12<1>(w1,b1,w2,t,n,s_feat,s_h1c,acc); break;
        case 2: gno_l12<2>(w1,b1,w2,t,n,s_feat,s_h1c,acc); break;
        case 3: gno_l12<3>(w1,b1,w2,t,n,s_feat,s_h1c,acc); break;
        case 4: gno_l12<4>(w1,b1,w2,t,n,s_feat,s_h1c,acc); break;
        case 5: gno_l12<5>(w1,b1,w2,t,n,s_feat,s_h1c,acc); break;
        case 6: gno_l12<6>(w1,b1,w2,t,n,s_feat,s_h1c,acc); break;
        default: break;
    }
    // h2 = gelu(acc + b2), transposed store [k][p]
    {
        float bb = b2[t];
        #pragma unroll
        for (int p=0;p<KK;p++){
            float v = 0.f;
            if (p < n) v = dgelu(acc[p] + bb);
            s_h2[t*H2S + p] = v;
        }
    }
    __syncthreads();
    // layer3: thread (c2 = t&63, pg = t>>6) owns 12 contiguous p; h2 reads warp-broadcast
    {
        int c2 = t & 63, pg = t >> 6;
        float local = 0.f;
        if (pg*12 < n){
            float a3[12];
            #pragma unroll
            for (int j=0;j<12;j++) a3[j] = 0.f;
            const float* w3c = w3 + c2;
            for (int k=0;k<GH2;k++){
                float wv = w3c[(size_t)k*64];
                const float* hr = &s_h2[k*H2S + pg*12];
                const float4 h0 = *(const float4*)(hr);
                const float4 h1 = *(const float4*)(hr+4);
                const float4 h2v = *(const float4*)(hr+8);
                a3[0] += h0.x*wv; a3[1] += h0.y*wv; a3[2] += h0.z*wv; a3[3] += h0.w*wv;
                a3[4] += h1.x*wv; a3[5] += h1.y*wv; a3[6] += h1.z*wv; a3[7] += h1.w*wv;
                a3[8] += h2v.x*wv; a3[9] += h2v.y*wv; a3[10] += h2v.z*wv; a3[11] += h2v.w*wv;
            }
            float bb = b3[c2];
            #pragma unroll
            for (int j=0;j<12;j++){
                int p = pg*12 + j;
                if (p < n){
                    int idx = g_nbr[q*KK + p];
                    local += (a3[j] + bb) * g_x[idx*64 + c2];
                }
            }
        }
        s_red[pg*64 + c2] = local;
    }
    __syncthreads();
    if (t < 64){
        float s = s_red[t] + s_red[64+t] + s_red[128+t] + s_red[192+t];
        float cd = (float)(n > 0 ? n : 1);
        g_gno[q*64 + t] = s / cd;
    }
}

// ---------------- projection: 64 -> 256 (gelu) -> 1 ----------------
__global__ void __launch_bounds__(256) k_proj(const float* __restrict__ pw1,
                                              const float* __restrict__ pb1,
                                              const float* __restrict__ pw2,
                                              const float* __restrict__ pb2,
                                              float* __restrict__ out){
    __shared__ float s_g[32*64];
    __shared__ float s_h[32*256];
    int t = threadIdx.x, qb = blockIdx.x*32;
    for (int i=0;i<8;i++) s_g[t+i*256] = g_gno[qb*64 + t + i*256];
    __syncthreads();
    int c = t;
    float b = pb1[c], wv = pw2[c];
    for (int q=0;q<32;q++){
        float acc = b;
        #pragma unroll 8
        for (int j=0;j<64;j++) acc += s_g[q*64+j]*pw1[j*256+c];
        s_h[q*256+c] = dgelu(acc)*wv;
    }
    __syncthreads();
    if (t < 32){
        float s = pb2[0];
        const float* hr = &s_h[t*256];
        for (int k=0;k<256;k++) s += hr[k];
        out[qb + t] = s;
    }
}

// ---------------- launch ----------------
extern "C" void kernel_launch(void* const* d_in, const int* in_sizes, int n_in,
                              void* d_out, int out_size){
    static const int expA[21] = {98304,12288,98304,1536,256,16384,64,33554432,
                                 256,16384,256,3072,512,131072,256,16384,64,
                                 16384,256,256,1};
    float* out = (float*)d_out;
    int ok = (n_in == 21);
    for (int i = 0; i < 21 && ok; i++) if (in_sizes[i] != expA[i]) ok = 0;
    if (!ok){
        k_zero<<<(out_size + 255)/256, 256>>>(out, out_size);
        return;
    }

    const float* in_p  = (const float*)d_in[0];
    const float* out_p = (const float*)d_in[1];
    const float* f     = (const float*)d_in[2];
    const float* lw1   = (const float*)d_in[3];
    const float* lb1   = (const float*)d_in[4];
    const float* lw2   = (const float*)d_in[5];
    const float* lb2   = (const float*)d_in[6];
    const float* W     = (const float*)d_in[7];
    const float* specb = (const float*)d_in[8];
    const float* skw   = (const float*)d_in[9];
    const float* skb   = (const float*)d_in[10];
    const float* gw1   = (const float*)d_in[11];
    const float* gb1   = (const float*)d_in[12];
    const float* gw2   = (const float*)d_in[13];
    const float* gb2   = (const float*)d_in[14];
    const float* gw3   = (const float*)d_in[15];
    const float* gb3   = (const float*)d_in[16];
    const float* pw1   = (const float*)d_in[17];
    const float* pb1   = (const float*)d_in[18];
    const float* pw2   = (const float*)d_in[19];
    const float* pb2   = (const float*)d_in[20];

    int gno_smem = (KK*KCH + GH2*H2S) * (int)sizeof(float);  // 65536
    cudaFuncSetAttribute(k_gno, cudaFuncAttributeMaxDynamicSharedMemorySize, gno_smem);

    k_lift<<<NP/8, 256>>>(f, in_p, lw1, lb1, lw2, lb2);
    for (int l = 0; l < LL; l++){
        int sel = l & 1;  // 0: read g_x write g_y; 1: read g_y write g_x
        k_fz<<<1024, 256>>>(sel);
        k_fy<<<256, 256>>>();
        k_fx<<<128, 256>>>();
        k_spec<<<512, 256>>>(W, l);
        k_ix<<<128, 256>>>();
        k_iy<<<256, 256>>>();
        k_iz<<<1024, 256>>>(specb, skw, skb, l, sel);
    }
    // latent now in g_x (l=3 writes g_x)
    k_nbr<<<NOUT/QPB, 128>>>(in_p, out_p);
    k_gno<<<NOUT, 256, gno_smem>>>(in_p, out_p, gw1, gb1, gw2, gb2, gw3, gb3);
    k_proj<<<NOUT/32, 256>>>(pw1, pb1, pw2, pb2, out);
}

// round 13
// speedup vs baseline: 3.9956x; 1.4297x over previous
#include <cuda_runtime.h>
#include <cuda_bf16.h>
#include <math.h>

#define DD 32
#define NP 32768
#define HH 64
#define MM 8
#define LL 4
#define KK 48
#define NOUT 4096
#define GH1 512
#define GH2 256
#define CANDCAP 96
#define R2 0.0036f
#define PI2 6.283185307179586f
#define FSC (1.0f/32768.0f)
#define QPB 8          // queries per nbr block
#define H1S 68         // h1 smem row stride (conflict-free A frags)
#define H2S 52         // h2 smem row stride (conflict-free epilogue stores)

// ---------------- device scratch ----------------
__device__ float  g_x[NP*HH];
__device__ float  g_y[NP*HH];
__device__ float2 g_s1[DD*DD*MM*HH];
__device__ float2 g_s2[DD*16*MM*HH];
__device__ float2 g_s3[16*16*MM*HH];
__device__ float2 g_s4[16*16*MM*HH];
__device__ float2 g_i1[DD*16*MM*HH];
__device__ float2 g_i2[DD*DD*MM*HH];
__device__ int    g_nbr[NOUT*KK];
__device__ int    g_cnt[NOUT];
__device__ float  g_gno[NOUT*HH];

// gelu(x) = x * sigmoid(2u); exp-based fast path, ~1e-7 accuracy.
__device__ __forceinline__ float dgelu(float x){
    float u = 1.5957691216057308f*(x + 0.044715f*x*x*x);
    return x * __fdividef(1.f, 1.f + __expf(-u));
}

// twiddle folded to [-pi,pi]
__device__ __forceinline__ void tw32(int m, float sign, float* s, float* c){
    int km = ((m & 31) + 15 & 31) - 15;
    __sincosf(sign*(PI2/32.f)*(float)km, s, c);
}

__device__ __forceinline__ unsigned f2tf32(float x){
    unsigned r;
    asm("cvt.rna.tf32.f32 %0, %1;" : "=r"(r) : "f"(x));
    return r;
}

__global__ void k_zero(float* out, int n){
    int i = blockIdx.x*256 + threadIdx.x;
    if (i < n) out[i] = 0.f;
}

// ---------------- lift: 6 -> 256 (gelu) -> 64 ----------------
__global__ void __launch_bounds__(256) k_lift(const float* __restrict__ f,
                                              const float* __restrict__ in_p,
                                              const float* __restrict__ w1,
                                              const float* __restrict__ b1,
                                              const float* __restrict__ w2,
                                              const float* __restrict__ b2){
    __shared__ float s_in[8][6];
    __shared__ float s_h1[8*256];
    int t = threadIdx.x;
    int pb = blockIdx.x*8;
    if (t < 48){
        int pp = t/6, k = t%6;
        int p = pb + pp;
        s_in[pp][k] = (k < 3) ? f[p*3+k] : in_p[p*3+(k-3)];
    }
    __syncthreads();
    float bb = b1[t];
    for (int pp=0; pp<8; pp++){
        float h = bb;
        #pragma unroll
        for (int k=0;k<6;k++) h += s_in[pp][k]*w1[k*256+t];
        s_h1[pp*256+t] = dgelu(h);
    }
    __syncthreads();
    for (int r=0;r<2;r++){
        int e = t + r*256;
        int pp = e>>6, c = e&63;
        float acc = b2[c];
        const float* h1 = &s_h1[pp*256];
        for (int k=0;k<256;k++) acc += h1[k]*w2[k*64+c];
        g_x[(pb+pp)*64+c] = acc;
    }
}

// ---------------- forward z-DFT ----------------
__global__ void __launch_bounds__(256) k_fz(int sel){
    const float* cur = sel ? g_y : g_x;
    __shared__ float sx[32*64];
    __shared__ float twr[8*32], twi[8*32];
    int t = threadIdx.x, bx = blockIdx.x;
    for (int i=0;i<8;i++) sx[t+i*256] = cur[bx*2048 + t + i*256];
    {
        int kz = t>>5, z = t&31;
        float s,c; tw32(kz*z, -1.f, &s, &c);
        twr[t] = c*FSC; twi[t] = s*FSC;
    }
    __syncthreads();
    for (int r=0;r<2;r++){
        int e = t + r*256;
        int kz = e>>6, c = e&63;
        float re=0.f, im=0.f;
        #pragma unroll
        for (int z=0; z<32; z++){
            float v = sx[z*64+c];
            re += v*twr[kz*32+z];
            im += v*twi[kz*32+z];
        }
        g_s1[(bx*8+kz)*64+c] = make_float2(re, im);
    }
}

// ---------------- forward y-DFT ----------------
__global__ void __launch_bounds__(256) k_fy(){
    __shared__ float2 sa[32*64];
    __shared__ float twr[16*32], twi[16*32];
    int t = threadIdx.x, bx = blockIdx.x;
    int ix = bx>>3, kz = bx&7;
    for (int i=0;i<8;i++){
        int e = t + i*256; int yy = e>>6, c = e&63;
        sa[e] = g_s1[((ix*32+yy)*8+kz)*64+c];
    }
    for (int i=0;i<2;i++){
        int e = t + i*256; int m = e>>5, yy = e&31;
        int k = (m<8)?m:(m+16);
        float s,c; tw32(k*yy, -1.f, &s, &c);
        twr[e]=c; twi[e]=s;
    }
    __syncthreads();
    for (int r=0;r<4;r++){
        int e = t + r*256;
        int m = e>>6, c = e&63;
        float re=0.f, im=0.f;
        #pragma unroll
        for (int yy=0;yy<32;yy++){
            float2 a = sa[yy*64+c];
            float wr = twr[m*32+yy], wi = twi[m*32+yy];
            re += a.x*wr - a.y*wi;
            im += a.x*wi + a.y*wr;
        }
        g_s2[((ix*16+m)*8+kz)*64+c] = make_float2(re, im);
    }
}

// ---------------- forward x-DFT ----------------
__global__ void __launch_bounds__(256) k_fx(){
    __shared__ float2 sa[32*64];
    __shared__ float twr[16*32], twi[16*32];
    int t = threadIdx.x, bx = blockIdx.x;
    int ky = bx>>3, kz = bx&7;
    for (int i=0;i<8;i++){
        int e = t + i*256; int x = e>>6, c = e&63;
        sa[e] = g_s2[((x*16+ky)*8+kz)*64+c];
    }
    for (int i=0;i<2;i++){
        int e = t + i*256; int m = e>>5, x = e&31;
        int k = (m<8)?m:(m+16);
        float s,c; tw32(k*x, -1.f, &s, &c);
        twr[e]=c; twi[e]=s;
    }
    __syncthreads();
    for (int r=0;r<4;r++){
        int e = t + r*256;
        int m = e>>6, c = e&63;
        float re=0.f, im=0.f;
        #pragma unroll
        for (int x=0;x<32;x++){
            float2 a = sa[x*64+c];
            float wr = twr[m*32+x], wi = twi[m*32+x];
            re += a.x*wr - a.y*wi;
            im += a.x*wi + a.y*wr;
        }
        g_s3[((m*16+ky)*8+kz)*64+c] = make_float2(re, im);
    }
}

// ---------------- spectral multiply, REAL weights; 512 blocks ----------------
__global__ void __launch_bounds__(256) k_spec(const float* __restrict__ W, int l){
    __shared__ float2 sx[64*8];  // [i][mz]
    int t = threadIdx.x, b = blockIdx.x;
    int half = b & 1, bb = b >> 1;
    int ci = bb>>6, mx = (bb>>3)&7, my = bb&7;
    int hx = ci>>1, hy = ci&1;
    int gx = mx + 8*hx, gy = my + 8*hy;
    for (int e = t; e < 512; e += 256){
        int i = e>>3, mz = e&7;
        sx[i*8+mz] = g_s3[((gx*16+gy)*8+mz)*64 + i];
    }
    __syncthreads();
    int mz = t&7, oh = (t>>3) + half*32;
    int moff = mx*64 + my*8 + mz;
    size_t base = (size_t)(l*4+ci)*64*64*512 + (size_t)moff + (size_t)oh*512;
    float ar=0.f, ai=0.f;
    #pragma unroll 8
    for (int i=0;i<64;i++){
        float2 xv = sx[i*8+mz];
        float w = W[base + (size_t)i*32768];
        ar += xv.x*w;  ai += xv.y*w;
    }
    g_s4[((gx*16+gy)*8+mz)*64 + oh] = make_float2(ar, ai);
}

// ---------------- inverse x ----------------
__global__ void __launch_bounds__(256) k_ix(){
    __shared__ float2 sa[16*64];
    __shared__ float twr[16*32], twi[16*32];
    int t = threadIdx.x, bx = blockIdx.x;
    int ky = bx>>3, kz = bx&7;
    for (int i=0;i<4;i++){
        int e = t + i*256; int m = e>>6, c = e&63;
        sa[e] = g_s4[((m*16+ky)*8+kz)*64+c];
    }
    for (int i=0;i<2;i++){
        int e = t + i*256; int m = e>>5, x = e&31;
        int k = (m<8)?m:(m+16);
        float s,c; tw32(k*x, 1.f, &s, &c);
        twr[e]=c; twi[e]=s;
    }
    __syncthreads();
    for (int r=0;r<8;r++){
        int e = t + r*256;
        int x = e>>6, c = e&63;
        float re=0.f, im=0.f;
        #pragma unroll
        for (int m=0;m<16;m++){
            float2 a = sa[m*64+c];
            float wr = twr[m*32+x], wi = twi[m*32+x];
            re += a.x*wr - a.y*wi;
            im += a.x*wi + a.y*wr;
        }
        g_i1[((x*16+ky)*8+kz)*64+c] = make_float2(re, im);
    }
}

// ---------------- inverse y ----------------
__global__ void __launch_bounds__(256) k_iy(){
    __shared__ float2 sa[16*64];
    __shared__ float twr[16*32], twi[16*32];
    int t = threadIdx.x, bx = blockIdx.x;
    int x = bx>>3, kz = bx&7;
    for (int i=0;i<4;i++){
        int e = t + i*256; int m = e>>6, c = e&63;
        sa[e] = g_i1[((x*16+m)*8+kz)*64+c];
    }
    for (int i=0;i<2;i++){
        int e = t + i*256; int m = e>>5, yy = e&31;
        int k = (m<8)?m:(m+16);
        float s,c; tw32(k*yy, 1.f, &s, &c);
        twr[e]=c; twi[e]=s;
    }
    __syncthreads();
    for (int r=0;r<8;r++){
        int e = t + r*256;
        int yy = e>>6, c = e&63;
        float re=0.f, im=0.f;
        #pragma unroll
        for (int m=0;m<16;m++){
            float2 a = sa[m*64+c];
            float wr = twr[m*32+yy], wi = twi[m*32+yy];
            re += a.x*wr - a.y*wi;
            im += a.x*wi + a.y*wr;
        }
        g_i2[((x*32+yy)*8+kz)*64+c] = make_float2(re, im);
    }
}

// ---------------- inverse z (c2r) + spec_b + skip GEMM + skip_b + gelu ----------------
__global__ void __launch_bounds__(256) k_iz(const float* __restrict__ spec_b,
                                            const float* __restrict__ skip_w,
                                            const float* __restrict__ skip_b,
                                            int l, int sel){
    const float* cur = sel ? g_y : g_x;
    float* dst = sel ? g_x : g_y;
    __shared__ float2 sza[8*64];
    __shared__ float  sxi[32*64];
    __shared__ float  ssw[64*64];
    __shared__ float  twr[8*32], twi[8*32];
    int t = threadIdx.x, bx = blockIdx.x;
    for (int i=0;i<2;i++){ int e=t+i*256; sza[e] = g_i2[(bx*8+(e>>6))*64+(e&63)]; }
    for (int i=0;i<8;i++)  sxi[t+i*256] = cur[bx*2048 + t + i*256];
    for (int i=0;i<16;i++) ssw[t+i*256] = skip_w[l*4096 + t + i*256];
    {
        int kz = t>>5, z = t&31;
        float s,c; tw32(kz*z, 1.f, &s, &c);
        twr[t]=c; twi[t]=s;
    }
    __syncthreads();
    for (int r=0;r<8;r++){
        int e = t + r*256;
        int z = e>>6, c = e&63;
        float acc = sza[c].x;
        #pragma unroll
        for (int k=1;k<8;k++){
            float2 a = sza[k*64+c];
            acc += 2.f*(a.x*twr[k*32+z] - a.y*twi[k*32+z]);
        }
        acc += spec_b[l*64+c] + skip_b[l*64+c];
        float sk = 0.f;
        #pragma unroll 8
        for (int j=0;j<64;j++) sk += sxi[z*64+j]*ssw[j*64+c];
        float v = acc + sk;
        if (l < 3) v = dgelu(v);
        dst[bx*2048 + z*64 + c] = v;
    }
}

// ---------------- neighbor search: 8 queries per block ----------------
__global__ void __launch_bounds__(128) k_nbr(const float* __restrict__ in_p,
                                             const float* __restrict__ out_p){
    __shared__ float s_d2[QPB][CANDCAP];
    __shared__ int   s_idx[QPB][CANDCAP];
    __shared__ int   s_n[QPB];
    __shared__ float s_q[QPB][3];
    int t = threadIdx.x;
    int q0 = blockIdx.x*QPB;
    if (t < QPB*3) s_q[t/3][t%3] = out_p[(q0 + t/3)*3 + (t%3)];
    if (t < QPB) s_n[t] = 0;
    __syncthreads();
    for (int p = t; p < NP; p += 128){
        float px = in_p[p*3+0], py = in_p[p*3+1], pz = in_p[p*3+2];
        #pragma unroll
        for (int qi=0; qi<QPB; qi++){
            float dx = s_q[qi][0]-px, dy = s_q[qi][1]-py, dz = s_q[qi][2]-pz;
            float d2 = dx*dx + dy*dy + dz*dz;
            if (d2 < R2){
                int pos = atomicAdd(&s_n[qi], 1);
                if (pos < CANDCAP){ s_d2[qi][pos] = d2; s_idx[qi][pos] = p; }
            }
        }
    }
    __syncthreads();
    if (t < QPB){
        int qi = t;
        int n = s_n[qi]; if (n > CANDCAP) n = CANDCAP;
        if (n > KK){
            for (int j = 0; j < KK; j++){
                int mi = j; float mv = s_d2[qi][j];
                for (int i = j+1; i < n; i++)
                    if (s_d2[qi][i] < mv){ mv = s_d2[qi][i]; mi = i; }
                float td = s_d2[qi][j]; s_d2[qi][j] = s_d2[qi][mi]; s_d2[qi][mi] = td;
                int   ti = s_idx[qi][j]; s_idx[qi][j] = s_idx[qi][mi]; s_idx[qi][mi] = ti;
            }
            n = KK;
        }
        g_cnt[q0 + qi] = n;
        s_n[qi] = n;
    }
    __syncthreads();
    for (int e = t; e < QPB*KK; e += 128){
        int qi = e / KK, j = e % KK;
        g_nbr[(q0+qi)*KK + j] = (j < s_n[qi]) ? s_idx[qi][j] : 0;
    }
}

// ---------------- GNO: layer2 on tf32 mma.sync ----------------
// dyn smem floats: h1c [48][H1S]=3264, h2 [GH2][H2S]=13312 -> 66304 B
extern __shared__ float gno_dyn[];
__global__ void __launch_bounds__(256, 3) k_gno(const float* __restrict__ in_p,
                                                const float* __restrict__ out_p,
                                                const float* __restrict__ w1,
                                                const float* __restrict__ b1,
                                                const float* __restrict__ w2,
                                                const float* __restrict__ b2,
                                                const float* __restrict__ w3,
                                                const float* __restrict__ b3){
    float* s_h1c = gno_dyn;                 // [p][H1S], 48 rows x 64 k
    float* s_h2  = gno_dyn + KK*H1S;        // [n][H2S], 256 rows x 48 p
    __shared__ float s_feat[KK*6];
    __shared__ float s_red[4*64];
    int t = threadIdx.x, q = blockIdx.x;
    int warp = t>>5, lane = t&31;
    int g = lane>>2, lr = lane&3;
    int nn = g_cnt[q];
    if (t < KK){
        int idx = g_nbr[q*KK + t];
        s_feat[t*6+0] = in_p[idx*3+0];
        s_feat[t*6+1] = in_p[idx*3+1];
        s_feat[t*6+2] = in_p[idx*3+2];
        s_feat[t*6+3] = out_p[q*3+0];
        s_feat[t*6+4] = out_p[q*3+1];
        s_feat[t*6+5] = out_p[q*3+2];
    }
    // accumulators: 3 m-tiles x 4 n-tiles x 4 f32
    float acc[12][4];
    #pragma unroll
    for (int i=0;i<12;i++){ acc[i][0]=0.f; acc[i][1]=0.f; acc[i][2]=0.f; acc[i][3]=0.f; }
    __syncthreads();

    for (int cc = 0; cc < 8; cc++){
        // layer1 chunk: h1c[p][kk], zero for p >= nn
        for (int e = t; e < KK*64; e += 256){
            int p = e>>6, kk = e&63;
            int k = cc*64 + kk;
            float v = 0.f;
            if (p < nn){
                float h = b1[k];
                #pragma unroll
                for (int j=0;j<6;j++) h += s_feat[p*6+j]*w1[j*GH1+k];
                v = dgelu(h);
            }
            s_h1c[p*H1S + kk] = v;
        }
        __syncthreads();
        // layer2 via m16n8k8 tf32: warp owns n in [warp*32, warp*32+32)
        const float* w2c = w2 + (size_t)(cc*64)*GH2;
        #pragma unroll
        for (int kt=0; kt<8; kt++){
            int k0 = kt*8;
            unsigned A[3][4];
            #pragma unroll
            for (int mt=0; mt<3; mt++){
                const float* ap = &s_h1c[(mt*16+g)*H1S + k0 + lr];
                A[mt][0] = f2tf32(ap[0]);
                A[mt][1] = f2tf32(ap[8*H1S]);
                A[mt][2] = f2tf32(ap[4]);
                A[mt][3] = f2tf32(ap[8*H1S+4]);
            }
            #pragma unroll
            for (int nt=0; nt<4; nt++){
                int n0 = warp*32 + nt*8;
                const float* bp = &w2c[(size_t)(k0+lr)*GH2 + n0 + g];
                unsigned B0 = f2tf32(bp[0]);
                unsigned B1 = f2tf32(bp[4*GH2]);
                #pragma unroll
                for (int mt=0; mt<3; mt++){
                    asm volatile(
                        "mma.sync.aligned.m16n8k8.row.col.f32.tf32.tf32.f32 "
                        "{%0,%1,%2,%3}, {%4,%5,%6,%7}, {%8,%9}, {%0,%1,%2,%3};"
                        : "+f"(acc[mt*4+nt][0]), "+f"(acc[mt*4+nt][1]),
                          "+f"(acc[mt*4+nt][2]), "+f"(acc[mt*4+nt][3])
                        : "r"(A[mt][0]), "r"(A[mt][1]), "r"(A[mt][2]), "r"(A[mt][3]),
                          "r"(B0), "r"(B1));
                }
            }
        }
        __syncthreads();
    }
    // epilogue: h2[n][p] = gelu(acc + b2[n]) masked by p < nn
    #pragma unroll
    for (int mt=0; mt<3; mt++){
        int p0 = mt*16 + g, p1 = p0 + 8;
        #pragma unroll
        for (int nt=0; nt<4; nt++){
            int n0 = warp*32 + nt*8 + 2*lr;
            float b20 = b2[n0], b21 = b2[n0+1];
            float* r0 = &s_h2[n0*H2S];
            float* r1 = &s_h2[(n0+1)*H2S];
            r0[p0] = (p0 < nn) ? dgelu(acc[mt*4+nt][0] + b20) : 0.f;
            r1[p0] = (p0 < nn) ? dgelu(acc[mt*4+nt][1] + b21) : 0.f;
            r0[p1] = (p1 < nn) ? dgelu(acc[mt*4+nt][2] + b20) : 0.f;
            r1[p1] = (p1 < nn) ? dgelu(acc[mt*4+nt][3] + b21) : 0.f;
        }
    }
    __syncthreads();
    // layer3: thread (c2 = t&63, pg = t>>6) owns 12 contiguous p
    {
        int c2 = t & 63, pg = t >> 6;
        float local = 0.f;
        if (pg*12 < nn){
            float a3[12];
            #pragma unroll
            for (int j=0;j<12;j++) a3[j] = 0.f;
            const float* w3c = w3 + c2;
            for (int k=0;k<GH2;k++){
                float wv = w3c[(size_t)k*64];
                const float* hr = &s_h2[k*H2S + pg*12];
                const float4 h0 = *(const float4*)(hr);
                const float4 h1 = *(const float4*)(hr+4);
                const float4 h2v = *(const float4*)(hr+8);
                a3[0] += h0.x*wv; a3[1] += h0.y*wv; a3[2] += h0.z*wv; a3[3] += h0.w*wv;
                a3[4] += h1.x*wv; a3[5] += h1.y*wv; a3[6] += h1.z*wv; a3[7] += h1.w*wv;
                a3[8] += h2v.x*wv; a3[9] += h2v.y*wv; a3[10] += h2v.z*wv; a3[11] += h2v.w*wv;
            }
            float bb = b3[c2];
            #pragma unroll
            for (int j=0;j<12;j++){
                int p = pg*12 + j;
                if (p < nn){
                    int idx = g_nbr[q*KK + p];
                    local += (a3[j] + bb) * g_x[idx*64 + c2];
                }
            }
        }
        s_red[pg*64 + c2] = local;
    }
    __syncthreads();
    if (t < 64){
        float s = s_red[t] + s_red[64+t] + s_red[128+t] + s_red[192+t];
        float cd = (float)(nn > 0 ? nn : 1);
        g_gno[q*64 + t] = s / cd;
    }
}

// ---------------- projection: 64 -> 256 (gelu) -> 1 ----------------
__global__ void __launch_bounds__(256) k_proj(const float* __restrict__ pw1,
                                              const float* __restrict__ pb1,
                                              const float* __restrict__ pw2,
                                              const float* __restrict__ pb2,
                                              float* __restrict__ out){
    __shared__ float s_g[32*64];
    __shared__ float s_h[32*256];
    int t = threadIdx.x, qb = blockIdx.x*32;
    for (int i=0;i<8;i++) s_g[t+i*256] = g_gno[qb*64 + t + i*256];
    __syncthreads();
    int c = t;
    float b = pb1[c], wv = pw2[c];
    for (int q=0;q<32;q++){
        float acc = b;
        #pragma unroll 8
        for (int j=0;j<64;j++) acc += s_g[q*64+j]*pw1[j*256+c];
        s_h[q*256+c] = dgelu(acc)*wv;
    }
    __syncthreads();
    if (t < 32){
        float s = pb2[0];
        const float* hr = &s_h[t*256];
        for (int k=0;k<256;k++) s += hr[k];
        out[qb + t] = s;
    }
}

// ---------------- launch ----------------
extern "C" void kernel_launch(void* const* d_in, const int* in_sizes, int n_in,
                              void* d_out, int out_size){
    static const int expA[21] = {98304,12288,98304,1536,256,16384,64,33554432,
                                 256,16384,256,3072,512,131072,256,16384,64,
                                 16384,256,256,1};
    float* out = (float*)d_out;
    int ok = (n_in == 21);
    for (int i = 0; i < 21 && ok; i++) if (in_sizes[i] != expA[i]) ok = 0;
    if (!ok){
        k_zero<<<(out_size + 255)/256, 256>>>(out, out_size);
        return;
    }

    const float* in_p  = (const float*)d_in[0];
    const float* out_p = (const float*)d_in[1];
    const float* f     = (const float*)d_in[2];
    const float* lw1   = (const float*)d_in[3];
    const float* lb1   = (const float*)d_in[4];
    const float* lw2   = (const float*)d_in[5];
    const float* lb2   = (const float*)d_in[6];
    const float* W     = (const float*)d_in[7];
    const float* specb = (const float*)d_in[8];
    const float* skw   = (const float*)d_in[9];
    const float* skb   = (const float*)d_in[10];
    const float* gw1   = (const float*)d_in[11];
    const float* gb1   = (const float*)d_in[12];
    const float* gw2   = (const float*)d_in[13];
    const float* gb2   = (const float*)d_in[14];
    const float* gw3   = (const float*)d_in[15];
    const float* gb3   = (const float*)d_in[16];
    const float* pw1   = (const float*)d_in[17];
    const float* pb1   = (const float*)d_in[18];
    const float* pw2   = (const float*)d_in[19];
    const float* pb2   = (const float*)d_in[20];

    int gno_smem = (KK*H1S + GH2*H2S) * (int)sizeof(float);  // 66304
    cudaFuncSetAttribute(k_gno, cudaFuncAttributeMaxDynamicSharedMemorySize, gno_smem);

    k_lift<<<NP/8, 256>>>(f, in_p, lw1, lb1, lw2, lb2);
    for (int l = 0; l < LL; l++){
        int sel = l & 1;  // 0: read g_x write g_y; 1: read g_y write g_x
        k_fz<<<1024, 256>>>(sel);
        k_fy<<<256, 256>>>();
        k_fx<<<128, 256>>>();
        k_spec<<<512, 256>>>(W, l);
        k_ix<<<128, 256>>>();
        k_iy<<<256, 256>>>();
        k_iz<<<1024, 256>>>(specb, skw, skb, l, sel);
    }
    // latent now in g_x (l=3 writes g_x)
    k_nbr<<<NOUT/QPB, 128>>>(in_p, out_p);
    k_gno<<<NOUT, 256, gno_smem>>>(in_p, out_p, gw1, gb1, gw2, gb2, gw3, gb3);
    k_proj<<<NOUT/32, 256>>>(pw1, pb1, pw2, pb2, out);
}

// round 14
// speedup vs baseline: 4.3109x; 1.0789x over previous
#include <cuda_runtime.h>
#include <cuda_bf16.h>
#include <math.h>

#define DD 32
#define NP 32768
#define HH 64
#define MM 8
#define LL 4
#define KK 48
#define NOUT 4096
#define GH1 512
#define GH2 256
#define CANDCAP 96
#define R2 0.0036f
#define PI2 6.283185307179586f
#define FSC (1.0f/32768.0f)
#define QPB 8          // queries per nbr block
#define H1S 68         // h1 smem row stride (conflict-free A frags)
#define H2K 260        // h2 [p][k] smem row stride (conflict-free A frags)

// ---------------- device scratch ----------------
__device__ float  g_x[NP*HH];
__device__ float  g_y[NP*HH];
__device__ float2 g_s1[DD*DD*MM*HH];
__device__ float2 g_s2[DD*16*MM*HH];
__device__ float2 g_s3[16*16*MM*HH];
__device__ float2 g_s4[16*16*MM*HH];
__device__ float2 g_i1[DD*16*MM*HH];
__device__ float2 g_i2[DD*DD*MM*HH];
__device__ int    g_nbr[NOUT*KK];
__device__ int    g_cnt[NOUT];
__device__ float  g_gno[NOUT*HH];

// gelu(x) = x * sigmoid(2u); exp-based fast path, ~1e-7 accuracy.
__device__ __forceinline__ float dgelu(float x){
    float u = 1.5957691216057308f*(x + 0.044715f*x*x*x);
    return x * __fdividef(1.f, 1.f + __expf(-u));
}

// twiddle folded to [-pi,pi]
__device__ __forceinline__ void tw32(int m, float sign, float* s, float* c){
    int km = ((m & 31) + 15 & 31) - 15;
    __sincosf(sign*(PI2/32.f)*(float)km, s, c);
}

__device__ __forceinline__ unsigned f2tf32(float x){
    unsigned r;
    asm("cvt.rna.tf32.f32 %0, %1;" : "=r"(r) : "f"(x));
    return r;
}

__global__ void k_zero(float* out, int n){
    int i = blockIdx.x*256 + threadIdx.x;
    if (i < n) out[i] = 0.f;
}

// ---------------- lift: 6 -> 256 (gelu) -> 64 ----------------
__global__ void __launch_bounds__(256) k_lift(const float* __restrict__ f,
                                              const float* __restrict__ in_p,
                                              const float* __restrict__ w1,
                                              const float* __restrict__ b1,
                                              const float* __restrict__ w2,
                                              const float* __restrict__ b2){
    __shared__ float s_in[8][6];
    __shared__ float s_h1[8*256];
    int t = threadIdx.x;
    int pb = blockIdx.x*8;
    if (t < 48){
        int pp = t/6, k = t%6;
        int p = pb + pp;
        s_in[pp][k] = (k < 3) ? f[p*3+k] : in_p[p*3+(k-3)];
    }
    __syncthreads();
    float bb = b1[t];
    for (int pp=0; pp<8; pp++){
        float h = bb;
        #pragma unroll
        for (int k=0;k<6;k++) h += s_in[pp][k]*w1[k*256+t];
        s_h1[pp*256+t] = dgelu(h);
    }
    __syncthreads();
    for (int r=0;r<2;r++){
        int e = t + r*256;
        int pp = e>>6, c = e&63;
        float acc = b2[c];
        const float* h1 = &s_h1[pp*256];
        for (int k=0;k<256;k++) acc += h1[k]*w2[k*64+c];
        g_x[(pb+pp)*64+c] = acc;
    }
}

// ---------------- forward z-DFT ----------------
__global__ void __launch_bounds__(256) k_fz(int sel){
    const float* cur = sel ? g_y : g_x;
    __shared__ float sx[32*64];
    __shared__ float twr[8*32], twi[8*32];
    int t = threadIdx.x, bx = blockIdx.x;
    for (int i=0;i<8;i++) sx[t+i*256] = cur[bx*2048 + t + i*256];
    {
        int kz = t>>5, z = t&31;
        float s,c; tw32(kz*z, -1.f, &s, &c);
        twr[t] = c*FSC; twi[t] = s*FSC;
    }
    __syncthreads();
    for (int r=0;r<2;r++){
        int e = t + r*256;
        int kz = e>>6, c = e&63;
        float re=0.f, im=0.f;
        #pragma unroll
        for (int z=0; z<32; z++){
            float v = sx[z*64+c];
            re += v*twr[kz*32+z];
            im += v*twi[kz*32+z];
        }
        g_s1[(bx*8+kz)*64+c] = make_float2(re, im);
    }
}

// ---------------- forward y-DFT ----------------
__global__ void __launch_bounds__(256) k_fy(){
    __shared__ float2 sa[32*64];
    __shared__ float twr[16*32], twi[16*32];
    int t = threadIdx.x, bx = blockIdx.x;
    int ix = bx>>3, kz = bx&7;
    for (int i=0;i<8;i++){
        int e = t + i*256; int yy = e>>6, c = e&63;
        sa[e] = g_s1[((ix*32+yy)*8+kz)*64+c];
    }
    for (int i=0;i<2;i++){
        int e = t + i*256; int m = e>>5, yy = e&31;
        int k = (m<8)?m:(m+16);
        float s,c; tw32(k*yy, -1.f, &s, &c);
        twr[e]=c; twi[e]=s;
    }
    __syncthreads();
    for (int r=0;r<4;r++){
        int e = t + r*256;
        int m = e>>6, c = e&63;
        float re=0.f, im=0.f;
        #pragma unroll
        for (int yy=0;yy<32;yy++){
            float2 a = sa[yy*64+c];
            float wr = twr[m*32+yy], wi = twi[m*32+yy];
            re += a.x*wr - a.y*wi;
            im += a.x*wi + a.y*wr;
        }
        g_s2[((ix*16+m)*8+kz)*64+c] = make_float2(re, im);
    }
}

// ---------------- forward x-DFT ----------------
__global__ void __launch_bounds__(256) k_fx(){
    __shared__ float2 sa[32*64];
    __shared__ float twr[16*32], twi[16*32];
    int t = threadIdx.x, bx = blockIdx.x;
    int ky = bx>>3, kz = bx&7;
    for (int i=0;i<8;i++){
        int e = t + i*256; int x = e>>6, c = e&63;
        sa[e] = g_s2[((x*16+ky)*8+kz)*64+c];
    }
    for (int i=0;i<2;i++){
        int e = t + i*256; int m = e>>5, x = e&31;
        int k = (m<8)?m:(m+16);
        float s,c; tw32(k*x, -1.f, &s, &c);
        twr[e]=c; twi[e]=s;
    }
    __syncthreads();
    for (int r=0;r<4;r++){
        int e = t + r*256;
        int m = e>>6, c = e&63;
        float re=0.f, im=0.f;
        #pragma unroll
        for (int x=0;x<32;x++){
            float2 a = sa[x*64+c];
            float wr = twr[m*32+x], wi = twi[m*32+x];
            re += a.x*wr - a.y*wi;
            im += a.x*wi + a.y*wr;
        }
        g_s3[((m*16+ky)*8+kz)*64+c] = make_float2(re, im);
    }
}

// ---------------- spectral multiply, REAL weights; 512 blocks ----------------
__global__ void __launch_bounds__(256) k_spec(const float* __restrict__ W, int l){
    __shared__ float2 sx[64*8];  // [i][mz]
    int t = threadIdx.x, b = blockIdx.x;
    int half = b & 1, bb = b >> 1;
    int ci = bb>>6, mx = (bb>>3)&7, my = bb&7;
    int hx = ci>>1, hy = ci&1;
    int gx = mx + 8*hx, gy = my + 8*hy;
    for (int e = t; e < 512; e += 256){
        int i = e>>3, mz = e&7;
        sx[i*8+mz] = g_s3[((gx*16+gy)*8+mz)*64 + i];
    }
    __syncthreads();
    int mz = t&7, oh = (t>>3) + half*32;
    int moff = mx*64 + my*8 + mz;
    size_t base = (size_t)(l*4+ci)*64*64*512 + (size_t)moff + (size_t)oh*512;
    float ar=0.f, ai=0.f;
    #pragma unroll 8
    for (int i=0;i<64;i++){
        float2 xv = sx[i*8+mz];
        float w = W[base + (size_t)i*32768];
        ar += xv.x*w;  ai += xv.y*w;
    }
    g_s4[((gx*16+gy)*8+mz)*64 + oh] = make_float2(ar, ai);
}

// ---------------- inverse x ----------------
__global__ void __launch_bounds__(256) k_ix(){
    __shared__ float2 sa[16*64];
    __shared__ float twr[16*32], twi[16*32];
    int t = threadIdx.x, bx = blockIdx.x;
    int ky = bx>>3, kz = bx&7;
    for (int i=0;i<4;i++){
        int e = t + i*256; int m = e>>6, c = e&63;
        sa[e] = g_s4[((m*16+ky)*8+kz)*64+c];
    }
    for (int i=0;i<2;i++){
        int e = t + i*256; int m = e>>5, x = e&31;
        int k = (m<8)?m:(m+16);
        float s,c; tw32(k*x, 1.f, &s, &c);
        twr[e]=c; twi[e]=s;
    }
    __syncthreads();
    for (int r=0;r<8;r++){
        int e = t + r*256;
        int x = e>>6, c = e&63;
        float re=0.f, im=0.f;
        #pragma unroll
        for (int m=0;m<16;m++){
            float2 a = sa[m*64+c];
            float wr = twr[m*32+x], wi = twi[m*32+x];
            re += a.x*wr - a.y*wi;
            im += a.x*wi + a.y*wr;
        }
        g_i1[((x*16+ky)*8+kz)*64+c] = make_float2(re, im);
    }
}

// ---------------- inverse y ----------------
__global__ void __launch_bounds__(256) k_iy(){
    __shared__ float2 sa[16*64];
    __shared__ float twr[16*32], twi[16*32];
    int t = threadIdx.x, bx = blockIdx.x;
    int x = bx>>3, kz = bx&7;
    for (int i=0;i<4;i++){
        int e = t + i*256; int m = e>>6, c = e&63;
        sa[e] = g_i1[((x*16+m)*8+kz)*64+c];
    }
    for (int i=0;i<2;i++){
        int e = t + i*256; int m = e>>5, yy = e&31;
        int k = (m<8)?m:(m+16);
        float s,c; tw32(k*yy, 1.f, &s, &c);
        twr[e]=c; twi[e]=s;
    }
    __syncthreads();
    for (int r=0;r<8;r++){
        int e = t + r*256;
        int yy = e>>6, c = e&63;
        float re=0.f, im=0.f;
        #pragma unroll
        for (int m=0;m<16;m++){
            float2 a = sa[m*64+c];
            float wr = twr[m*32+yy], wi = twi[m*32+yy];
            re += a.x*wr - a.y*wi;
            im += a.x*wi + a.y*wr;
        }
        g_i2[((x*32+yy)*8+kz)*64+c] = make_float2(re, im);
    }
}

// ---------------- inverse z (c2r) + spec_b + skip GEMM + skip_b + gelu ----------------
__global__ void __launch_bounds__(256) k_iz(const float* __restrict__ spec_b,
                                            const float* __restrict__ skip_w,
                                            const float* __restrict__ skip_b,
                                            int l, int sel){
    const float* cur = sel ? g_y : g_x;
    float* dst = sel ? g_x : g_y;
    __shared__ float2 sza[8*64];
    __shared__ float  sxi[32*64];
    __shared__ float  ssw[64*64];
    __shared__ float  twr[8*32], twi[8*32];
    int t = threadIdx.x, bx = blockIdx.x;
    for (int i=0;i<2;i++){ int e=t+i*256; sza[e] = g_i2[(bx*8+(e>>6))*64+(e&63)]; }
    for (int i=0;i<8;i++)  sxi[t+i*256] = cur[bx*2048 + t + i*256];
    for (int i=0;i<16;i++) ssw[t+i*256] = skip_w[l*4096 + t + i*256];
    {
        int kz = t>>5, z = t&31;
        float s,c; tw32(kz*z, 1.f, &s, &c);
        twr[t]=c; twi[t]=s;
    }
    __syncthreads();
    for (int r=0;r<8;r++){
        int e = t + r*256;
        int z = e>>6, c = e&63;
        float acc = sza[c].x;
        #pragma unroll
        for (int k=1;k<8;k++){
            float2 a = sza[k*64+c];
            acc += 2.f*(a.x*twr[k*32+z] - a.y*twi[k*32+z]);
        }
        acc += spec_b[l*64+c] + skip_b[l*64+c];
        float sk = 0.f;
        #pragma unroll 8
        for (int j=0;j<64;j++) sk += sxi[z*64+j]*ssw[j*64+c];
        float v = acc + sk;
        if (l < 3) v = dgelu(v);
        dst[bx*2048 + z*64 + c] = v;
    }
}

// ---------------- neighbor search: 8 queries per block ----------------
__global__ void __launch_bounds__(128) k_nbr(const float* __restrict__ in_p,
                                             const float* __restrict__ out_p){
    __shared__ float s_d2[QPB][CANDCAP];
    __shared__ int   s_idx[QPB][CANDCAP];
    __shared__ int   s_n[QPB];
    __shared__ float s_q[QPB][3];
    int t = threadIdx.x;
    int q0 = blockIdx.x*QPB;
    if (t < QPB*3) s_q[t/3][t%3] = out_p[(q0 + t/3)*3 + (t%3)];
    if (t < QPB) s_n[t] = 0;
    __syncthreads();
    for (int p = t; p < NP; p += 128){
        float px = in_p[p*3+0], py = in_p[p*3+1], pz = in_p[p*3+2];
        #pragma unroll
        for (int qi=0; qi<QPB; qi++){
            float dx = s_q[qi][0]-px, dy = s_q[qi][1]-py, dz = s_q[qi][2]-pz;
            float d2 = dx*dx + dy*dy + dz*dz;
            if (d2 < R2){
                int pos = atomicAdd(&s_n[qi], 1);
                if (pos < CANDCAP){ s_d2[qi][pos] = d2; s_idx[qi][pos] = p; }
            }
        }
    }
    __syncthreads();
    if (t < QPB){
        int qi = t;
        int n = s_n[qi]; if (n > CANDCAP) n = CANDCAP;
        if (n > KK){
            for (int j = 0; j < KK; j++){
                int mi = j; float mv = s_d2[qi][j];
                for (int i = j+1; i < n; i++)
                    if (s_d2[qi][i] < mv){ mv = s_d2[qi][i]; mi = i; }
                float td = s_d2[qi][j]; s_d2[qi][j] = s_d2[qi][mi]; s_d2[qi][mi] = td;
                int   ti = s_idx[qi][j]; s_idx[qi][j] = s_idx[qi][mi]; s_idx[qi][mi] = ti;
            }
            n = KK;
        }
        g_cnt[q0 + qi] = n;
        s_n[qi] = n;
    }
    __syncthreads();
    for (int e = t; e < QPB*KK; e += 128){
        int qi = e / KK, j = e % KK;
        g_nbr[(q0+qi)*KK + j] = (j < s_n[qi]) ? s_idx[qi][j] : 0;
    }
}

// ---------------- GNO: layers 2 AND 3 on tf32 mma.sync ----------------
// dyn smem floats: h1c [48][H1S]=3264 (reused for a3), h2p [48][H2K]=12480 -> 62976 B
extern __shared__ float gno_dyn[];
__global__ void __launch_bounds__(256, 3) k_gno(const float* __restrict__ in_p,
                                                const float* __restrict__ out_p,
                                                const float* __restrict__ w1,
                                                const float* __restrict__ b1,
                                                const float* __restrict__ w2,
                                                const float* __restrict__ b2,
                                                const float* __restrict__ w3,
                                                const float* __restrict__ b3){
    float* s_h1c = gno_dyn;                 // [p][H1S]; later reused as a3 [p][H1S]
    float* s_h2p = gno_dyn + KK*H1S;        // [p][H2K], 48 rows x 256 k
    __shared__ float s_feat[KK*6];
    __shared__ float s_red[4*64];
    int t = threadIdx.x, q = blockIdx.x;
    int warp = t>>5, lane = t&31;
    int g = lane>>2, lr = lane&3;
    int nn = g_cnt[q];
    if (t < KK){
        int idx = g_nbr[q*KK + t];
        s_feat[t*6+0] = in_p[idx*3+0];
        s_feat[t*6+1] = in_p[idx*3+1];
        s_feat[t*6+2] = in_p[idx*3+2];
        s_feat[t*6+3] = out_p[q*3+0];
        s_feat[t*6+4] = out_p[q*3+1];
        s_feat[t*6+5] = out_p[q*3+2];
    }
    // layer2 accumulators: 3 m-tiles x 4 n-tiles x 4 f32
    float acc[12][4];
    #pragma unroll
    for (int i=0;i<12;i++){ acc[i][0]=0.f; acc[i][1]=0.f; acc[i][2]=0.f; acc[i][3]=0.f; }
    __syncthreads();

    for (int cc = 0; cc < 8; cc++){
        // layer1 chunk: h1c[p][kk], zero for p >= nn
        for (int e = t; e < KK*64; e += 256){
            int p = e>>6, kk = e&63;
            int k = cc*64 + kk;
            float v = 0.f;
            if (p < nn){
                float h = b1[k];
                #pragma unroll
                for (int j=0;j<6;j++) h += s_feat[p*6+j]*w1[j*GH1+k];
                v = dgelu(h);
            }
            s_h1c[p*H1S + kk] = v;
        }
        __syncthreads();
        // layer2 via m16n8k8 tf32: warp owns n in [warp*32, warp*32+32)
        const float* w2c = w2 + (size_t)(cc*64)*GH2;
        #pragma unroll
        for (int kt=0; kt<8; kt++){
            int k0 = kt*8;
            unsigned A[3][4];
            #pragma unroll
            for (int mt=0; mt<3; mt++){
                const float* ap = &s_h1c[(mt*16+g)*H1S + k0 + lr];
                A[mt][0] = f2tf32(ap[0]);
                A[mt][1] = f2tf32(ap[8*H1S]);
                A[mt][2] = f2tf32(ap[4]);
                A[mt][3] = f2tf32(ap[8*H1S+4]);
            }
            #pragma unroll
            for (int nt=0; nt<4; nt++){
                int n0 = warp*32 + nt*8;
                const float* bp = &w2c[(size_t)(k0+lr)*GH2 + n0 + g];
                unsigned B0 = f2tf32(bp[0]);
                unsigned B1 = f2tf32(bp[4*GH2]);
                #pragma unroll
                for (int mt=0; mt<3; mt++){
                    asm volatile(
                        "mma.sync.aligned.m16n8k8.row.col.f32.tf32.tf32.f32 "
                        "{%0,%1,%2,%3}, {%4,%5,%6,%7}, {%8,%9}, {%0,%1,%2,%3};"
                        : "+f"(acc[mt*4+nt][0]), "+f"(acc[mt*4+nt][1]),
                          "+f"(acc[mt*4+nt][2]), "+f"(acc[mt*4+nt][3])
                        : "r"(A[mt][0]), "r"(A[mt][1]), "r"(A[mt][2]), "r"(A[mt][3]),
                          "r"(B0), "r"(B1));
                }
            }
        }
        __syncthreads();
    }
    // layer2 epilogue: h2p[p][n] = gelu(acc + b2[n]) masked by p < nn   ([p][k] layout!)
    #pragma unroll
    for (int mt=0; mt<3; mt++){
        int p0 = mt*16 + g, p1 = p0 + 8;
        float* r0 = &s_h2p[p0*H2K];
        float* r1 = &s_h2p[p1*H2K];
        #pragma unroll
        for (int nt=0; nt<4; nt++){
            int n0 = warp*32 + nt*8 + 2*lr;
            float b20 = b2[n0], b21 = b2[n0+1];
            r0[n0]   = (p0 < nn) ? dgelu(acc[mt*4+nt][0] + b20) : 0.f;
            r0[n0+1] = (p0 < nn) ? dgelu(acc[mt*4+nt][1] + b21) : 0.f;
            r1[n0]   = (p1 < nn) ? dgelu(acc[mt*4+nt][2] + b20) : 0.f;
            r1[n0+1] = (p1 < nn) ? dgelu(acc[mt*4+nt][3] + b21) : 0.f;
        }
    }
    __syncthreads();
    // layer3 via m16n8k8 tf32: D[48][64] = h2p[48][256] * w3[256][64]
    // warp owns n-tile n0 = warp*8; 3 m-tiles; 32 k-steps
    float acc3[3][4];
    #pragma unroll
    for (int i=0;i<3;i++){ acc3[i][0]=0.f; acc3[i][1]=0.f; acc3[i][2]=0.f; acc3[i][3]=0.f; }
    #pragma unroll 8
    for (int kt=0; kt<32; kt++){
        int k0 = kt*8;
        unsigned A[3][4];
        #pragma unroll
        for (int mt=0; mt<3; mt++){
            const float* ap = &s_h2p[(mt*16+g)*H2K + k0 + lr];
            A[mt][0] = f2tf32(ap[0]);
            A[mt][1] = f2tf32(ap[8*H2K]);
            A[mt][2] = f2tf32(ap[4]);
            A[mt][3] = f2tf32(ap[8*H2K+4]);
        }
        const float* bp = &w3[(size_t)(k0+lr)*64 + warp*8 + g];
        unsigned B0 = f2tf32(bp[0]);
        unsigned B1 = f2tf32(bp[4*64]);
        #pragma unroll
        for (int mt=0; mt<3; mt++){
            asm volatile(
                "mma.sync.aligned.m16n8k8.row.col.f32.tf32.tf32.f32 "
                "{%0,%1,%2,%3}, {%4,%5,%6,%7}, {%8,%9}, {%0,%1,%2,%3};"
                : "+f"(acc3[mt][0]), "+f"(acc3[mt][1]),
                  "+f"(acc3[mt][2]), "+f"(acc3[mt][3])
                : "r"(A[mt][0]), "r"(A[mt][1]), "r"(A[mt][2]), "r"(A[mt][3]),
                  "r"(B0), "r"(B1));
        }
    }
    __syncthreads();   // all warps done reading s_h2p / s_h1c reuse safe
    // store a3 into s_h1c as [p][H1S] (c in 0..63)
    #pragma unroll
    for (int mt=0; mt<3; mt++){
        int p0 = mt*16 + g, p1 = p0 + 8;
        int c0 = warp*8 + 2*lr;
        s_h1c[p0*H1S + c0]   = acc3[mt][0];
        s_h1c[p0*H1S + c0+1] = acc3[mt][1];
        s_h1c[p1*H1S + c0]   = acc3[mt][2];
        s_h1c[p1*H1S + c0+1] = acc3[mt][3];
    }
    __syncthreads();
    // fy multiply + reduce: thread (c2 = t&63, pg = t>>6) owns 12 contiguous p
    {
        int c2 = t & 63, pg = t >> 6;
        float local = 0.f;
        if (pg*12 < nn){
            float bb = b3[c2];
            #pragma unroll
            for (int j=0;j<12;j++){
                int p = pg*12 + j;
                if (p < nn){
                    int idx = g_nbr[q*KK + p];
                    local += (s_h1c[p*H1S + c2] + bb) * g_x[idx*64 + c2];
                }
            }
        }
        s_red[pg*64 + c2] = local;
    }
    __syncthreads();
    if (t < 64){
        float s = s_red[t] + s_red[64+t] + s_red[128+t] + s_red[192+t];
        float cd = (float)(nn > 0 ? nn : 1);
        g_gno[q*64 + t] = s / cd;
    }
}

// ---------------- projection: 64 -> 256 (gelu) -> 1 ----------------
__global__ void __launch_bounds__(256) k_proj(const float* __restrict__ pw1,
                                              const float* __restrict__ pb1,
                                              const float* __restrict__ pw2,
                                              const float* __restrict__ pb2,
                                              float* __restrict__ out){
    __shared__ float s_g[32*64];
    __shared__ float s_h[32*256];
    int t = threadIdx.x, qb = blockIdx.x*32;
    for (int i=0;i<8;i++) s_g[t+i*256] = g_gno[qb*64 + t + i*256];
    __syncthreads();
    int c = t;
    float b = pb1[c], wv = pw2[c];
    for (int q=0;q<32;q++){
        float acc = b;
        #pragma unroll 8
        for (int j=0;j<64;j++) acc += s_g[q*64+j]*pw1[j*256+c];
        s_h[q*256+c] = dgelu(acc)*wv;
    }
    __syncthreads();
    if (t < 32){
        float s = pb2[0];
        const float* hr = &s_h[t*256];
        for (int k=0;k<256;k++) s += hr[k];
        out[qb + t] = s;
    }
}

// ---------------- launch ----------------
extern "C" void kernel_launch(void* const* d_in, const int* in_sizes, int n_in,
                              void* d_out, int out_size){
    static const int expA[21] = {98304,12288,98304,1536,256,16384,64,33554432,
                                 256,16384,256,3072,512,131072,256,16384,64,
                                 16384,256,256,1};
    float* out = (float*)d_out;
    int ok = (n_in == 21);
    for (int i = 0; i < 21 && ok; i++) if (in_sizes[i] != expA[i]) ok = 0;
    if (!ok){
        k_zero<<<(out_size + 255)/256, 256>>>(out, out_size);
        return;
    }

    const float* in_p  = (const float*)d_in[0];
    const float* out_p = (const float*)d_in[1];
    const float* f     = (const float*)d_in[2];
    const float* lw1   = (const float*)d_in[3];
    const float* lb1   = (const float*)d_in[4];
    const float* lw2   = (const float*)d_in[5];
    const float* lb2   = (const float*)d_in[6];
    const float* W     = (const float*)d_in[7];
    const float* specb = (const float*)d_in[8];
    const float* skw   = (const float*)d_in[9];
    const float* skb   = (const float*)d_in[10];
    const float* gw1   = (const float*)d_in[11];
    const float* gb1   = (const float*)d_in[12];
    const float* gw2   = (const float*)d_in[13];
    const float* gb2   = (const float*)d_in[14];
    const float* gw3   = (const float*)d_in[15];
    const float* gb3   = (const float*)d_in[16];
    const float* pw1   = (const float*)d_in[17];
    const float* pb1   = (const float*)d_in[18];
    const float* pw2   = (const float*)d_in[19];
    const float* pb2   = (const float*)d_in[20];

    int gno_smem = (KK*H1S + KK*H2K) * (int)sizeof(float);  // 62976
    cudaFuncSetAttribute(k_gno, cudaFuncAttributeMaxDynamicSharedMemorySize, gno_smem);

    k_lift<<<NP/8, 256>>>(f, in_p, lw1, lb1, lw2, lb2);
    for (int l = 0; l < LL; l++){
        int sel = l & 1;  // 0: read g_x write g_y; 1: read g_y write g_x
        k_fz<<<1024, 256>>>(sel);
        k_fy<<<256, 256>>>();
        k_fx<<<128, 256>>>();
        k_spec<<<512, 256>>>(W, l);
        k_ix<<<128, 256>>>();
        k_iy<<<256, 256>>>();
        k_iz<<<1024, 256>>>(specb, skw, skb, l, sel);
    }
    // latent now in g_x (l=3 writes g_x)
    k_nbr<<<NOUT/QPB, 128>>>(in_p, out_p);
    k_gno<<<NOUT, 256, gno_smem>>>(in_p, out_p, gw1, gb1, gw2, gb2, gw3, gb3);
    k_proj<<<NOUT/32, 256>>>(pw1, pb1, pw2, pb2, out);
}

// round 15
// speedup vs baseline: 5.2883x; 1.2267x over previous
#include <cuda_runtime.h>
#include <cuda_bf16.h>
#include <math.h>

#define DD 32
#define NP 32768
#define HH 64
#define MM 8
#define LL 4
#define KK 48
#define NOUT 4096
#define GH1 512
#define GH2 256
#define CANDCAP 96
#define R2 0.0036f
#define PI2 6.283185307179586f
#define FSC (1.0f/32768.0f)
#define QPB 8          // queries per nbr block
#define H1S 68         // h1 smem row stride (conflict-free A frags)
#define H2K 260        // h2 [p][k] smem row stride (conflict-free A frags)

// ---------------- device scratch ----------------
__device__ float  g_x[NP*HH];
__device__ float  g_y[NP*HH];
__device__ float2 g_s1[DD*DD*MM*HH];
__device__ float2 g_s2[DD*16*MM*HH];
__device__ float2 g_s3[16*16*MM*HH];
__device__ float2 g_s4[16*16*MM*HH];
__device__ float2 g_i1[DD*16*MM*HH];
__device__ float2 g_i2[DD*DD*MM*HH];
__device__ int    g_nbr[NOUT*KK];
__device__ int    g_cnt[NOUT];
__device__ float  g_gno[NOUT*HH];
__device__ float  g_w2t[65536*2];   // packed tf32 w2: [kb(64)][n(256)][lr(4)] -> (k_lo,k_hi)
__device__ float  g_w3t[8192*2];    // packed tf32 w3: [kb(32)][n(64)][lr(4)] -> (k_lo,k_hi)

// gelu(x) = x * sigmoid(2u); exp-based fast path, ~1e-7 accuracy.
__device__ __forceinline__ float dgelu(float x){
    float u = 1.5957691216057308f*(x + 0.044715f*x*x*x);
    return x * __fdividef(1.f, 1.f + __expf(-u));
}

// twiddle folded to [-pi,pi]
__device__ __forceinline__ void tw32(int m, float sign, float* s, float* c){
    int km = ((m & 31) + 15 & 31) - 15;
    __sincosf(sign*(PI2/32.f)*(float)km, s, c);
}

__device__ __forceinline__ unsigned f2tf32(float x){
    unsigned r;
    asm("cvt.rna.tf32.f32 %0, %1;" : "=r"(r) : "f"(x));
    return r;
}

__global__ void k_zero(float* out, int n){
    int i = blockIdx.x*256 + threadIdx.x;
    if (i < n) out[i] = 0.f;
}

// ---------------- weight pre-pack: tf32-rounded, fragment-paired ----------------
__global__ void __launch_bounds__(256) k_pack(const float* __restrict__ w2,
                                              const float* __restrict__ w3){
    int i = blockIdx.x*256 + threadIdx.x;
    if (i < 65536){
        int kb = i >> 10;
        int rem = i & 1023;
        int n = rem >> 2, lr = rem & 3;
        float a = w2[(kb*8+lr)*GH2 + n];
        float b = w2[(kb*8+lr+4)*GH2 + n];
        g_w2t[i*2]   = __uint_as_float(f2tf32(a));
        g_w2t[i*2+1] = __uint_as_float(f2tf32(b));
    } else if (i < 65536 + 8192){
        int j = i - 65536;
        int kb = j >> 8;
        int rem = j & 255;
        int n = rem >> 2, lr = rem & 3;
        float a = w3[(kb*8+lr)*64 + n];
        float b = w3[(kb*8+lr+4)*64 + n];
        g_w3t[j*2]   = __uint_as_float(f2tf32(a));
        g_w3t[j*2+1] = __uint_as_float(f2tf32(b));
    }
}

// ---------------- lift: 6 -> 256 (gelu) -> 64 ----------------
__global__ void __launch_bounds__(256) k_lift(const float* __restrict__ f,
                                              const float* __restrict__ in_p,
                                              const float* __restrict__ w1,
                                              const float* __restrict__ b1,
                                              const float* __restrict__ w2,
                                              const float* __restrict__ b2){
    __shared__ float s_in[8][6];
    __shared__ float s_h1[8*256];
    int t = threadIdx.x;
    int pb = blockIdx.x*8;
    if (t < 48){
        int pp = t/6, k = t%6;
        int p = pb + pp;
        s_in[pp][k] = (k < 3) ? f[p*3+k] : in_p[p*3+(k-3)];
    }
    __syncthreads();
    float bb = b1[t];
    for (int pp=0; pp<8; pp++){
        float h = bb;
        #pragma unroll
        for (int k=0;k<6;k++) h += s_in[pp][k]*w1[k*256+t];
        s_h1[pp*256+t] = dgelu(h);
    }
    __syncthreads();
    for (int r=0;r<2;r++){
        int e = t + r*256;
        int pp = e>>6, c = e&63;
        float acc = b2[c];
        const float* h1 = &s_h1[pp*256];
        for (int k=0;k<256;k++) acc += h1[k]*w2[k*64+c];
        g_x[(pb+pp)*64+c] = acc;
    }
}

// ---------------- forward z-DFT ----------------
__global__ void __launch_bounds__(256) k_fz(int sel){
    const float* cur = sel ? g_y : g_x;
    __shared__ float sx[32*64];
    __shared__ float twr[8*32], twi[8*32];
    int t = threadIdx.x, bx = blockIdx.x;
    for (int i=0;i<8;i++) sx[t+i*256] = cur[bx*2048 + t + i*256];
    {
        int kz = t>>5, z = t&31;
        float s,c; tw32(kz*z, -1.f, &s, &c);
        twr[t] = c*FSC; twi[t] = s*FSC;
    }
    __syncthreads();
    for (int r=0;r<2;r++){
        int e = t + r*256;
        int kz = e>>6, c = e&63;
        float re=0.f, im=0.f;
        #pragma unroll
        for (int z=0; z<32; z++){
            float v = sx[z*64+c];
            re += v*twr[kz*32+z];
            im += v*twi[kz*32+z];
        }
        g_s1[(bx*8+kz)*64+c] = make_float2(re, im);
    }
}

// ---------------- forward y-DFT ----------------
__global__ void __launch_bounds__(256) k_fy(){
    __shared__ float2 sa[32*64];
    __shared__ float twr[16*32], twi[16*32];
    int t = threadIdx.x, bx = blockIdx.x;
    int ix = bx>>3, kz = bx&7;
    for (int i=0;i<8;i++){
        int e = t + i*256; int yy = e>>6, c = e&63;
        sa[e] = g_s1[((ix*32+yy)*8+kz)*64+c];
    }
    for (int i=0;i<2;i++){
        int e = t + i*256; int m = e>>5, yy = e&31;
        int k = (m<8)?m:(m+16);
        float s,c; tw32(k*yy, -1.f, &s, &c);
        twr[e]=c; twi[e]=s;
    }
    __syncthreads();
    for (int r=0;r<4;r++){
        int e = t + r*256;
        int m = e>>6, c = e&63;
        float re=0.f, im=0.f;
        #pragma unroll
        for (int yy=0;yy<32;yy++){
            float2 a = sa[yy*64+c];
            float wr = twr[m*32+yy], wi = twi[m*32+yy];
            re += a.x*wr - a.y*wi;
            im += a.x*wi + a.y*wr;
        }
        g_s2[((ix*16+m)*8+kz)*64+c] = make_float2(re, im);
    }
}

// ---------------- forward x-DFT ----------------
__global__ void __launch_bounds__(256) k_fx(){
    __shared__ float2 sa[32*64];
    __shared__ float twr[16*32], twi[16*32];
    int t = threadIdx.x, bx = blockIdx.x;
    int ky = bx>>3, kz = bx&7;
    for (int i=0;i<8;i++){
        int e = t + i*256; int x = e>>6, c = e&63;
        sa[e] = g_s2[((x*16+ky)*8+kz)*64+c];
    }
    for (int i=0;i<2;i++){
        int e = t + i*256; int m = e>>5, x = e&31;
        int k = (m<8)?m:(m+16);
        float s,c; tw32(k*x, -1.f, &s, &c);
        twr[e]=c; twi[e]=s;
    }
    __syncthreads();
    for (int r=0;r<4;r++){
        int e = t + r*256;
        int m = e>>6, c = e&63;
        float re=0.f, im=0.f;
        #pragma unroll
        for (int x=0;x<32;x++){
            float2 a = sa[x*64+c];
            float wr = twr[m*32+x], wi = twi[m*32+x];
            re += a.x*wr - a.y*wi;
            im += a.x*wi + a.y*wr;
        }
        g_s3[((m*16+ky)*8+kz)*64+c] = make_float2(re, im);
    }
}

// ---------------- spectral multiply, REAL weights; 512 blocks ----------------
__global__ void __launch_bounds__(256) k_spec(const float* __restrict__ W, int l){
    __shared__ float2 sx[64*8];  // [i][mz]
    int t = threadIdx.x, b = blockIdx.x;
    int half = b & 1, bb = b >> 1;
    int ci = bb>>6, mx = (bb>>3)&7, my = bb&7;
    int hx = ci>>1, hy = ci&1;
    int gx = mx + 8*hx, gy = my + 8*hy;
    for (int e = t; e < 512; e += 256){
        int i = e>>3, mz = e&7;
        sx[i*8+mz] = g_s3[((gx*16+gy)*8+mz)*64 + i];
    }
    __syncthreads();
    int mz = t&7, oh = (t>>3) + half*32;
    int moff = mx*64 + my*8 + mz;
    size_t base = (size_t)(l*4+ci)*64*64*512 + (size_t)moff + (size_t)oh*512;
    float ar=0.f, ai=0.f;
    #pragma unroll 8
    for (int i=0;i<64;i++){
        float2 xv = sx[i*8+mz];
        float w = W[base + (size_t)i*32768];
        ar += xv.x*w;  ai += xv.y*w;
    }
    g_s4[((gx*16+gy)*8+mz)*64 + oh] = make_float2(ar, ai);
}

// ---------------- inverse x ----------------
__global__ void __launch_bounds__(256) k_ix(){
    __shared__ float2 sa[16*64];
    __shared__ float twr[16*32], twi[16*32];
    int t = threadIdx.x, bx = blockIdx.x;
    int ky = bx>>3, kz = bx&7;
    for (int i=0;i<4;i++){
        int e = t + i*256; int m = e>>6, c = e&63;
        sa[e] = g_s4[((m*16+ky)*8+kz)*64+c];
    }
    for (int i=0;i<2;i++){
        int e = t + i*256; int m = e>>5, x = e&31;
        int k = (m<8)?m:(m+16);
        float s,c; tw32(k*x, 1.f, &s, &c);
        twr[e]=c; twi[e]=s;
    }
    __syncthreads();
    for (int r=0;r<8;r++){
        int e = t + r*256;
        int x = e>>6, c = e&63;
        float re=0.f, im=0.f;
        #pragma unroll
        for (int m=0;m<16;m++){
            float2 a = sa[m*64+c];
            float wr = twr[m*32+x], wi = twi[m*32+x];
            re += a.x*wr - a.y*wi;
            im += a.x*wi + a.y*wr;
        }
        g_i1[((x*16+ky)*8+kz)*64+c] = make_float2(re, im);
    }
}

// ---------------- inverse y ----------------
__global__ void __launch_bounds__(256) k_iy(){
    __shared__ float2 sa[16*64];
    __shared__ float twr[16*32], twi[16*32];
    int t = threadIdx.x, bx = blockIdx.x;
    int x = bx>>3, kz = bx&7;
    for (int i=0;i<4;i++){
        int e = t + i*256; int m = e>>6, c = e&63;
        sa[e] = g_i1[((x*16+m)*8+kz)*64+c];
    }
    for (int i=0;i<2;i++){
        int e = t + i*256; int m = e>>5, yy = e&31;
        int k = (m<8)?m:(m+16);
        float s,c; tw32(k*yy, 1.f, &s, &c);
        twr[e]=c; twi[e]=s;
    }
    __syncthreads();
    for (int r=0;r<8;r++){
        int e = t + r*256;
        int yy = e>>6, c = e&63;
        float re=0.f, im=0.f;
        #pragma unroll
        for (int m=0;m<16;m++){
            float2 a = sa[m*64+c];
            float wr = twr[m*32+yy], wi = twi[m*32+yy];
            re += a.x*wr - a.y*wi;
            im += a.x*wi + a.y*wr;
        }
        g_i2[((x*32+yy)*8+kz)*64+c] = make_float2(re, im);
    }
}

// ---------------- inverse z (c2r) + spec_b + skip GEMM + skip_b + gelu ----------------
__global__ void __launch_bounds__(256) k_iz(const float* __restrict__ spec_b,
                                            const float* __restrict__ skip_w,
                                            const float* __restrict__ skip_b,
                                            int l, int sel){
    const float* cur = sel ? g_y : g_x;
    float* dst = sel ? g_x : g_y;
    __shared__ float2 sza[8*64];
    __shared__ float  sxi[32*64];
    __shared__ float  ssw[64*64];
    __shared__ float  twr[8*32], twi[8*32];
    int t = threadIdx.x, bx = blockIdx.x;
    for (int i=0;i<2;i++){ int e=t+i*256; sza[e] = g_i2[(bx*8+(e>>6))*64+(e&63)]; }
    for (int i=0;i<8;i++)  sxi[t+i*256] = cur[bx*2048 + t + i*256];
    for (int i=0;i<16;i++) ssw[t+i*256] = skip_w[l*4096 + t + i*256];
    {
        int kz = t>>5, z = t&31;
        float s,c; tw32(kz*z, 1.f, &s, &c);
        twr[t]=c; twi[t]=s;
    }
    __syncthreads();
    for (int r=0;r<8;r++){
        int e = t + r*256;
        int z = e>>6, c = e&63;
        float acc = sza[c].x;
        #pragma unroll
        for (int k=1;k<8;k++){
            float2 a = sza[k*64+c];
            acc += 2.f*(a.x*twr[k*32+z] - a.y*twi[k*32+z]);
        }
        acc += spec_b[l*64+c] + skip_b[l*64+c];
        float sk = 0.f;
        #pragma unroll 8
        for (int j=0;j<64;j++) sk += sxi[z*64+j]*ssw[j*64+c];
        float v = acc + sk;
        if (l < 3) v = dgelu(v);
        dst[bx*2048 + z*64 + c] = v;
    }
}

// ---------------- neighbor search: 8 queries per block ----------------
__global__ void __launch_bounds__(128) k_nbr(const float* __restrict__ in_p,
                                             const float* __restrict__ out_p){
    __shared__ float s_d2[QPB][CANDCAP];
    __shared__ int   s_idx[QPB][CANDCAP];
    __shared__ int   s_n[QPB];
    __shared__ float s_q[QPB][3];
    int t = threadIdx.x;
    int q0 = blockIdx.x*QPB;
    if (t < QPB*3) s_q[t/3][t%3] = out_p[(q0 + t/3)*3 + (t%3)];
    if (t < QPB) s_n[t] = 0;
    __syncthreads();
    for (int p = t; p < NP; p += 128){
        float px = in_p[p*3+0], py = in_p[p*3+1], pz = in_p[p*3+2];
        #pragma unroll
        for (int qi=0; qi<QPB; qi++){
            float dx = s_q[qi][0]-px, dy = s_q[qi][1]-py, dz = s_q[qi][2]-pz;
            float d2 = dx*dx + dy*dy + dz*dz;
            if (d2 < R2){
                int pos = atomicAdd(&s_n[qi], 1);
                if (pos < CANDCAP){ s_d2[qi][pos] = d2; s_idx[qi][pos] = p; }
            }
        }
    }
    __syncthreads();
    if (t < QPB){
        int qi = t;
        int n = s_n[qi]; if (n > CANDCAP) n = CANDCAP;
        if (n > KK){
            for (int j = 0; j < KK; j++){
                int mi = j; float mv = s_d2[qi][j];
                for (int i = j+1; i < n; i++)
                    if (s_d2[qi][i] < mv){ mv = s_d2[qi][i]; mi = i; }
                float td = s_d2[qi][j]; s_d2[qi][j] = s_d2[qi][mi]; s_d2[qi][mi] = td;
                int   ti = s_idx[qi][j]; s_idx[qi][j] = s_idx[qi][mi]; s_idx[qi][mi] = ti;
            }
            n = KK;
        }
        g_cnt[q0 + qi] = n;
        s_n[qi] = n;
    }
    __syncthreads();
    for (int e = t; e < QPB*KK; e += 128){
        int qi = e / KK, j = e % KK;
        g_nbr[(q0+qi)*KK + j] = (j < s_n[qi]) ? s_idx[qi][j] : 0;
    }
}

// ---------------- GNO: layers 2+3 tf32 mma, pre-rounded operands, packed B ----------------
// dyn smem floats: h1c [48][H1S]=3264 (reused for a3), h2p [48][H2K]=12480 -> 62976 B
extern __shared__ float gno_dyn[];
__global__ void __launch_bounds__(256, 3) k_gno(const float* __restrict__ in_p,
                                                const float* __restrict__ out_p,
                                                const float* __restrict__ w1,
                                                const float* __restrict__ b1,
                                                const float* __restrict__ b2,
                                                const float* __restrict__ b3){
    float* s_h1c = gno_dyn;                 // [p][H1S] tf32 bits; later reused as a3 f32
    float* s_h2p = gno_dyn + KK*H1S;        // [p][H2K] tf32 bits
    __shared__ float s_feat[KK*6];
    __shared__ float s_red[4*64];
    int t = threadIdx.x, q = blockIdx.x;
    int warp = t>>5, lane = t&31;
    int g = lane>>2, lr = lane&3;
    int nn = g_cnt[q];
    if (t < KK){
        int idx = g_nbr[q*KK + t];
        s_feat[t*6+0] = in_p[idx*3+0];
        s_feat[t*6+1] = in_p[idx*3+1];
        s_feat[t*6+2] = in_p[idx*3+2];
        s_feat[t*6+3] = out_p[q*3+0];
        s_feat[t*6+4] = out_p[q*3+1];
        s_feat[t*6+5] = out_p[q*3+2];
    }
    float acc[12][4];
    #pragma unroll
    for (int i=0;i<12;i++){ acc[i][0]=0.f; acc[i][1]=0.f; acc[i][2]=0.f; acc[i][3]=0.f; }
    __syncthreads();

    const float2* w2t = (const float2*)g_w2t;
    const float2* w3t = (const float2*)g_w3t;

    for (int cc = 0; cc < 8; cc++){
        // layer1 chunk: h1c[p][kk] pre-rounded to tf32 bits; zero for p >= nn
        for (int e = t; e < KK*64; e += 256){
            int p = e>>6, kk = e&63;
            int k = cc*64 + kk;
            float v = 0.f;
            if (p < nn){
                float h = b1[k];
                #pragma unroll
                for (int j=0;j<6;j++) h += s_feat[p*6+j]*w1[j*GH1+k];
                v = __uint_as_float(f2tf32(dgelu(h)));
            }
            s_h1c[p*H1S + kk] = v;
        }
        __syncthreads();
        // layer2 via m16n8k8 tf32: warp owns n in [warp*32, warp*32+32)
        #pragma unroll
        for (int kt=0; kt<8; kt++){
            int k0 = kt*8;
            int kb = cc*8 + kt;
            unsigned A[3][4];
            #pragma unroll
            for (int mt=0; mt<3; mt++){
                const float* ap = &s_h1c[(mt*16+g)*H1S + k0 + lr];
                A[mt][0] = __float_as_uint(ap[0]);
                A[mt][1] = __float_as_uint(ap[8*H1S]);
                A[mt][2] = __float_as_uint(ap[4]);
                A[mt][3] = __float_as_uint(ap[8*H1S+4]);
            }
            #pragma unroll
            for (int nt=0; nt<4; nt++){
                int n0 = warp*32 + nt*8;
                float2 bv = w2t[(size_t)(kb*GH2 + n0 + g)*4 + lr];
                unsigned B0 = __float_as_uint(bv.x);
                unsigned B1 = __float_as_uint(bv.y);
                #pragma unroll
                for (int mt=0; mt<3; mt++){
                    asm volatile(
                        "mma.sync.aligned.m16n8k8.row.col.f32.tf32.tf32.f32 "
                        "{%0,%1,%2,%3}, {%4,%5,%6,%7}, {%8,%9}, {%0,%1,%2,%3};"
                        : "+f"(acc[mt*4+nt][0]), "+f"(acc[mt*4+nt][1]),
                          "+f"(acc[mt*4+nt][2]), "+f"(acc[mt*4+nt][3])
                        : "r"(A[mt][0]), "r"(A[mt][1]), "r"(A[mt][2]), "r"(A[mt][3]),
                          "r"(B0), "r"(B1));
                }
            }
        }
        __syncthreads();
    }
    // layer2 epilogue: h2p[p][n] = tf32(gelu(acc + b2[n])) masked by p < nn
    #pragma unroll
    for (int mt=0; mt<3; mt++){
        int p0 = mt*16 + g, p1 = p0 + 8;
        float* r0 = &s_h2p[p0*H2K];
        float* r1 = &s_h2p[p1*H2K];
        #pragma unroll
        for (int nt=0; nt<4; nt++){
            int n0 = warp*32 + nt*8 + 2*lr;
            float b20 = b2[n0], b21 = b2[n0+1];
            r0[n0]   = (p0 < nn) ? __uint_as_float(f2tf32(dgelu(acc[mt*4+nt][0] + b20))) : 0.f;
            r0[n0+1] = (p0 < nn) ? __uint_as_float(f2tf32(dgelu(acc[mt*4+nt][1] + b21))) : 0.f;
            r1[n0]   = (p1 < nn) ? __uint_as_float(f2tf32(dgelu(acc[mt*4+nt][2] + b20))) : 0.f;
            r1[n0+1] = (p1 < nn) ? __uint_as_float(f2tf32(dgelu(acc[mt*4+nt][3] + b21))) : 0.f;
        }
    }
    __syncthreads();
    // layer3 via m16n8k8 tf32: D[48][64] = h2p[48][256] * w3[256][64]
    float acc3[3][4];
    #pragma unroll
    for (int i=0;i<3;i++){ acc3[i][0]=0.f; acc3[i][1]=0.f; acc3[i][2]=0.f; acc3[i][3]=0.f; }
    #pragma unroll 8
    for (int kt=0; kt<32; kt++){
        int k0 = kt*8;
        unsigned A[3][4];
        #pragma unroll
        for (int mt=0; mt<3; mt++){
            const float* ap = &s_h2p[(mt*16+g)*H2K + k0 + lr];
            A[mt][0] = __float_as_uint(ap[0]);
            A[mt][1] = __float_as_uint(ap[8*H2K]);
            A[mt][2] = __float_as_uint(ap[4]);
            A[mt][3] = __float_as_uint(ap[8*H2K+4]);
        }
        float2 bv = w3t[(size_t)(kt*64 + warp*8 + g)*4 + lr];
        unsigned B0 = __float_as_uint(bv.x);
        unsigned B1 = __float_as_uint(bv.y);
        #pragma unroll
        for (int mt=0; mt<3; mt++){
            asm volatile(
                "mma.sync.aligned.m16n8k8.row.col.f32.tf32.tf32.f32 "
                "{%0,%1,%2,%3}, {%4,%5,%6,%7}, {%8,%9}, {%0,%1,%2,%3};"
                : "+f"(acc3[mt][0]), "+f"(acc3[mt][1]),
                  "+f"(acc3[mt][2]), "+f"(acc3[mt][3])
                : "r"(A[mt][0]), "r"(A[mt][1]), "r"(A[mt][2]), "r"(A[mt][3]),
                  "r"(B0), "r"(B1));
        }
    }
    __syncthreads();   // all warps done reading s_h2p; s_h1c reuse safe
    // store a3 into s_h1c as [p][H1S] (c in 0..63)
    #pragma unroll
    for (int mt=0; mt<3; mt++){
        int p0 = mt*16 + g, p1 = p0 + 8;
        int c0 = warp*8 + 2*lr;
        s_h1c[p0*H1S + c0]   = acc3[mt][0];
        s_h1c[p0*H1S + c0+1] = acc3[mt][1];
        s_h1c[p1*H1S + c0]   = acc3[mt][2];
        s_h1c[p1*H1S + c0+1] = acc3[mt][3];
    }
    __syncthreads();
    // fy multiply + reduce: thread (c2 = t&63, pg = t>>6) owns 12 contiguous p
    {
        int c2 = t & 63, pg = t >> 6;
        float local = 0.f;
        if (pg*12 < nn){
            float bb = b3[c2];
            #pragma unroll
            for (int j=0;j<12;j++){
                int p = pg*12 + j;
                if (p < nn){
                    int idx = g_nbr[q*KK + p];
                    local += (s_h1c[p*H1S + c2] + bb) * g_x[idx*64 + c2];
                }
            }
        }
        s_red[pg*64 + c2] = local;
    }
    __syncthreads();
    if (t < 64){
        float s = s_red[t] + s_red[64+t] + s_red[128+t] + s_red[192+t];
        float cd = (float)(nn > 0 ? nn : 1);
        g_gno[q*64 + t] = s / cd;
    }
}

// ---------------- projection: 64 -> 256 (gelu) -> 1 ----------------
__global__ void __launch_bounds__(256) k_proj(const float* __restrict__ pw1,
                                              const float* __restrict__ pb1,
                                              const float* __restrict__ pw2,
                                              const float* __restrict__ pb2,
                                              float* __restrict__ out){
    __shared__ float s_g[32*64];
    __shared__ float s_h[32*256];
    int t = threadIdx.x, qb = blockIdx.x*32;
    for (int i=0;i<8;i++) s_g[t+i*256] = g_gno[qb*64 + t + i*256];
    __syncthreads();
    int c = t;
    float b = pb1[c], wv = pw2[c];
    for (int q=0;q<32;q++){
        float acc = b;
        #pragma unroll 8
        for (int j=0;j<64;j++) acc += s_g[q*64+j]*pw1[j*256+c];
        s_h[q*256+c] = dgelu(acc)*wv;
    }
    __syncthreads();
    if (t < 32){
        float s = pb2[0];
        const float* hr = &s_h[t*256];
        for (int k=0;k<256;k++) s += hr[k];
        out[qb + t] = s;
    }
}

// ---------------- launch ----------------
extern "C" void kernel_launch(void* const* d_in, const int* in_sizes, int n_in,
                              void* d_out, int out_size){
    static const int expA[21] = {98304,12288,98304,1536,256,16384,64,33554432,
                                 256,16384,256,3072,512,131072,256,16384,64,
                                 16384,256,256,1};
    float* out = (float*)d_out;
    int ok = (n_in == 21);
    for (int i = 0; i < 21 && ok; i++) if (in_sizes[i] != expA[i]) ok = 0;
    if (!ok){
        k_zero<<<(out_size + 255)/256, 256>>>(out, out_size);
        return;
    }

    const float* in_p  = (const float*)d_in[0];
    const float* out_p = (const float*)d_in[1];
    const float* f     = (const float*)d_in[2];
    const float* lw1   = (const float*)d_in[3];
    const float* lb1   = (const float*)d_in[4];
    const float* lw2   = (const float*)d_in[5];
    const float* lb2   = (const float*)d_in[6];
    const float* W     = (const float*)d_in[7];
    const float* specb = (const float*)d_in[8];
    const float* skw   = (const float*)d_in[9];
    const float* skb   = (const float*)d_in[10];
    const float* gw1   = (const float*)d_in[11];
    const float* gb1   = (const float*)d_in[12];
    const float* gw2   = (const float*)d_in[13];
    const float* gb2   = (const float*)d_in[14];
    const float* gw3   = (const float*)d_in[15];
    const float* gb3   = (const float*)d_in[16];
    const float* pw1   = (const float*)d_in[17];
    const float* pb1   = (const float*)d_in[18];
    const float* pw2   = (const float*)d_in[19];
    const float* pb2   = (const float*)d_in[20];

    int gno_smem = (KK*H1S + KK*H2K) * (int)sizeof(float);  // 62976
    cudaFuncSetAttribute(k_gno, cudaFuncAttributeMaxDynamicSharedMemorySize, gno_smem);

    k_pack<<<288, 256>>>(gw2, gw3);
    k_lift<<<NP/8, 256>>>(f, in_p, lw1, lb1, lw2, lb2);
    for (int l = 0; l < LL; l++){
        int sel = l & 1;  // 0: read g_x write g_y; 1: read g_y write g_x
        k_fz<<<1024, 256>>>(sel);
        k_fy<<<256, 256>>>();
        k_fx<<<128, 256>>>();
        k_spec<<<512, 256>>>(W, l);
        k_ix<<<128, 256>>>();
        k_iy<<<256, 256>>>();
        k_iz<<<1024, 256>>>(specb, skw, skb, l, sel);
    }
    // latent now in g_x (l=3 writes g_x)
    k_nbr<<<NOUT/QPB, 128>>>(in_p, out_p);
    k_gno<<<NOUT, 256, gno_smem>>>(in_p, out_p, gw1, gb1, gb2, gb3);
    k_proj<<<NOUT/32, 256>>>(pw1, pb1, pw2, pb2, out);
}